// round 13
// baseline (speedup 1.0000x reference)
#include <cuda_runtime.h>
#include <cuda_bf16.h>
#include <math.h>

#define N_PTS   32768
#define K_EMB   8192
#define DIM     32
#define THREADS 256
#define NBLK    (N_PTS / THREADS)        // 128
#define PTS_PER_BLOCK 256                // 8 warps * 32 pts (2 A-tiles each)
#define PTGRPS  (N_PTS / PTS_PER_BLOCK)  // 128
#define CRANGES 8
#define CODES_PER_RANGE (K_EMB / CRANGES)   // 1024
#define TILE_C  256                       // codes per smem tile
#define ITEMS   (PTGRPS * CRANGES)        // 1024 blocks -> ~4 resident/SM
#define SROW    40                        // padded bf16 row stride
#define MARGIN  0.04f
#define CAP     (1u << 23)                // 8M candidate slots

// ---- scratch (device globals; no allocation allowed) ----
__device__ float          g_ew [K_EMB * DIM];    // normalized codes fp32
__device__ unsigned short g_ewh[K_EMB * DIM];    // normalized codes bf16 bits
__device__ float          g_zn [N_PTS * DIM];    // normalized points fp32
__device__ unsigned short g_znh[N_PTS * DIM];    // normalized points bf16 bits
__device__ unsigned int   g_maxu[N_PTS];         // sortable max approx dot
__device__ unsigned long long g_bestpk[N_PTS];   // packed (key(dot)<<32)|(8191-idx)
__device__ unsigned int   g_ncand;
__device__ unsigned int   g_cand[CAP];           // (pt<<13)|code
__device__ int   g_hist[K_EMB];
__device__ float g_part[NBLK];
__device__ float g_entp[32];

// ---- sortable float <-> u32 ----
__device__ __forceinline__ unsigned int fkey(float f) {
    unsigned int s = __float_as_uint(f);
    return (s & 0x80000000u) ? ~s : (s | 0x80000000u);
}
__device__ __forceinline__ float finv(unsigned int k) {
    unsigned int s = (k & 0x80000000u) ? (k ^ 0x80000000u) : ~k;
    return __uint_as_float(s);
}

// ---- m16n8k16 bf16 MMA, fp32 accum ----
__device__ __forceinline__ void hmma(float* c, const unsigned int* a,
                                     const unsigned int* b) {
    asm volatile(
        "mma.sync.aligned.m16n8k16.row.col.f32.bf16.bf16.f32 "
        "{%0,%1,%2,%3}, {%4,%5,%6,%7}, {%8,%9}, {%0,%1,%2,%3};"
        : "+f"(c[0]), "+f"(c[1]), "+f"(c[2]), "+f"(c[3])
        : "r"(a[0]), "r"(a[1]), "r"(a[2]), "r"(a[3]),
          "r"(b[0]), "r"(b[1]));
}

// ---- ldmatrix x4: all four B fragments in one LDSM (layout proven R10) ----
__device__ __forceinline__ void ldsm_x4(unsigned int* r, unsigned int addr) {
    asm volatile(
        "ldmatrix.sync.aligned.m8n8.x4.shared.b16 {%0,%1,%2,%3}, [%4];"
        : "=r"(r[0]), "=r"(r[1]), "=r"(r[2]), "=r"(r[3]) : "r"(addr));
}

__device__ __forceinline__ unsigned int smem_u32(const void* p) {
    return (unsigned int)__cvta_generic_to_shared(p);
}

// ---- candidate push (only past-threshold; ~few per point) ----
__device__ __forceinline__ void push_cand(int pt, int code) {
    unsigned int p = atomicAdd(&g_ncand, 1u);
    if (p < CAP)
        g_cand[p] = ((unsigned)pt << 13) | (unsigned)code;
}

// ============================================================
// Kernel 0: init scratch   (launch #1)
// ============================================================
__global__ void init_kernel() {
    int i = blockIdx.x * blockDim.x + threadIdx.x;   // 0..32767
    if (i < K_EMB) g_hist[i] = 0;
    g_maxu[i] = 0u;
    g_bestpk[i] = 0ull;
    if (i == 0) g_ncand = 0u;
}

// ============================================================
// Kernel 1: normalize embedding rows -> fp32 + bf16
// ============================================================
__global__ void prep_emb(const float* __restrict__ emb) {
    int r = blockIdx.x * blockDim.x + threadIdx.x;   // 0..8191

    const float4* src = reinterpret_cast<const float4*>(emb + r * DIM);
    float4 v[8];
    float s = 0.f;
#pragma unroll
    for (int i = 0; i < 8; i++) {
        v[i] = src[i];
        s += v[i].x * v[i].x + v[i].y * v[i].y + v[i].z * v[i].z + v[i].w * v[i].w;
    }
    float inv = 1.0f / fmaxf(sqrtf(s), 1e-12f);
    float4* dst = reinterpret_cast<float4*>(g_ew + r * DIM);
#pragma unroll
    for (int i = 0; i < 8; i++) {
        float4 o;
        o.x = v[i].x * inv; o.y = v[i].y * inv;
        o.z = v[i].z * inv; o.w = v[i].w * inv;
        dst[i] = o;
        g_ewh[r * DIM + 4 * i + 0] = __bfloat16_as_ushort(__float2bfloat16(o.x));
        g_ewh[r * DIM + 4 * i + 1] = __bfloat16_as_ushort(__float2bfloat16(o.y));
        g_ewh[r * DIM + 4 * i + 2] = __bfloat16_as_ushort(__float2bfloat16(o.z));
        g_ewh[r * DIM + 4 * i + 3] = __bfloat16_as_ushort(__float2bfloat16(o.w));
    }
}

// ============================================================
// Kernel 2: normalize points (bchw gather) -> fp32 + bf16
// ============================================================
__global__ void prep_z(const float* __restrict__ z) {
    int n = blockIdx.x * blockDim.x + threadIdx.x;   // 0..32767
    const int b  = n >> 10;
    const int hw = n & 1023;
    const float* zp = z + b * (DIM * 1024) + hw;
    float zn[DIM];
    float s = 0.f;
#pragma unroll
    for (int d = 0; d < DIM; d++) {
        float v = zp[d * 1024];
        zn[d] = v;
        s += v * v;
    }
    float inv = 1.0f / fmaxf(sqrtf(s), 1e-12f);
#pragma unroll
    for (int d = 0; d < DIM; d++) {
        float t = zn[d] * inv;
        g_zn [n * DIM + d] = t;
        g_znh[n * DIM + d] = __bfloat16_as_ushort(__float2bfloat16(t));
    }
}

// ---- shared fill helper (u32 packed bf16 pairs) ----
__device__ __forceinline__ void fill_tile(unsigned short* dst, // [rows][SROW]
                                          const unsigned short* src, // rows*DIM
                                          int rows, int tid) {
    const unsigned int* s32 = reinterpret_cast<const unsigned int*>(src);
    for (int idx = tid; idx < rows * (DIM / 2); idx += THREADS) {
        int r = idx >> 4, dp = idx & 15;
        *reinterpret_cast<unsigned int*>(&dst[r * SROW + dp * 2]) =
            s32[r * (DIM / 2) + dp];
    }
}

// ---- load the two k-half A fragments for one m16 tile (proven layout) ----
__device__ __forceinline__ void load_A(const unsigned short* sZ, int row,
                                       int qc, unsigned int* A0,
                                       unsigned int* A1) {
    A0[0] = *reinterpret_cast<const unsigned int*>(&sZ[row * SROW + qc]);
    A0[1] = *reinterpret_cast<const unsigned int*>(&sZ[(row + 8) * SROW + qc]);
    A0[2] = *reinterpret_cast<const unsigned int*>(&sZ[row * SROW + qc + 8]);
    A0[3] = *reinterpret_cast<const unsigned int*>(&sZ[(row + 8) * SROW + qc + 8]);
    A1[0] = *reinterpret_cast<const unsigned int*>(&sZ[row * SROW + qc + 16]);
    A1[1] = *reinterpret_cast<const unsigned int*>(&sZ[(row + 8) * SROW + qc + 16]);
    A1[2] = *reinterpret_cast<const unsigned int*>(&sZ[row * SROW + qc + 24]);
    A1[3] = *reinterpret_cast<const unsigned int*>(&sZ[(row + 8) * SROW + qc + 24]);
}

// ============================================================
// Kernel 3: PASS 1 — bf16 MMA sweep, per-point max approx dot
// 32 pts/warp; 4 INDEPENDENT HMMAs per LDSM (split accumulators,
// combined by FADD) -> 2x tensor ILP.  (launch #4 -> profiled)
// ============================================================
__global__ void __launch_bounds__(THREADS)
pass1_kernel() {
    __shared__ __align__(16) unsigned short sZ[PTS_PER_BLOCK * SROW]; // 20 KB
    __shared__ __align__(16) unsigned short sC[TILE_C * SROW];        // 20 KB

    const int tid  = threadIdx.x;
    const int w    = tid >> 5;
    const int lane = tid & 31;
    const int qr   = lane >> 2;          // 0..7
    const int qc   = (lane & 3) * 2;     // 0,2,4,6

    const unsigned int sc0 =
        smem_u32(sC) + ((lane & 7) * SROW + (lane >> 3) * 8) * 2;

    const int it = blockIdx.x;              // one item per block
    const int pg = it >> 3;                 // point group 0..127
    const int cr = it & 7;                  // code range 0..7
    const int p0 = pg * PTS_PER_BLOCK;
    const int c0r = cr * CODES_PER_RANGE;

    fill_tile(sZ, g_znh + p0 * DIM, PTS_PER_BLOCK, tid);
    __syncthreads();

    // two A tiles per warp: rows w*32 .. w*32+31
    const int ar0 = w * 32 + qr;
    const int ar1 = ar0 + 16;
    unsigned int A0[4], A1[4], A2[4], A3[4];
    load_A(sZ, ar0, qc, A0, A1);
    load_A(sZ, ar1, qc, A2, A3);

    float m0 = -2.0f, m1 = -2.0f, m2 = -2.0f, m3 = -2.0f;

    for (int t = 0; t < CODES_PER_RANGE; t += TILE_C) {
        __syncthreads();
        fill_tile(sC, g_ewh + (c0r + t) * DIM, TILE_C, tid);
        __syncthreads();

#pragma unroll 4
        for (int nt = 0; nt < TILE_C / 8; nt++) {
            unsigned int B[4];
            ldsm_x4(B, sc0 + nt * (8 * SROW * 2));   // all 4 B frags
            float ca[4] = {0.f, 0.f, 0.f, 0.f};   // pts tile0, k 0..15
            float cb[4] = {0.f, 0.f, 0.f, 0.f};   // pts tile0, k16..31
            float cc[4] = {0.f, 0.f, 0.f, 0.f};   // pts tile1, k 0..15
            float cd[4] = {0.f, 0.f, 0.f, 0.f};   // pts tile1, k16..31
            hmma(ca, A0, B);
            hmma(cb, A1, B + 2);
            hmma(cc, A2, B);
            hmma(cd, A3, B + 2);
            m0 = fmaxf(m0, fmaxf(ca[0] + cb[0], ca[1] + cb[1]));
            m1 = fmaxf(m1, fmaxf(ca[2] + cb[2], ca[3] + cb[3]));
            m2 = fmaxf(m2, fmaxf(cc[0] + cd[0], cc[1] + cd[1]));
            m3 = fmaxf(m3, fmaxf(cc[2] + cd[2], cc[3] + cd[3]));
        }
    }
    // reduce max over the 4 threads of each quad (cols)
#pragma unroll
    for (int x = 1; x < 4; x <<= 1) {
        m0 = fmaxf(m0, __shfl_xor_sync(0xFFFFFFFFu, m0, x));
        m1 = fmaxf(m1, __shfl_xor_sync(0xFFFFFFFFu, m1, x));
        m2 = fmaxf(m2, __shfl_xor_sync(0xFFFFFFFFu, m2, x));
        m3 = fmaxf(m3, __shfl_xor_sync(0xFFFFFFFFu, m3, x));
    }
    if ((lane & 3) == 0) {
        atomicMax(&g_maxu[p0 + ar0],      fkey(m0));
        atomicMax(&g_maxu[p0 + ar0 + 8],  fkey(m1));
        atomicMax(&g_maxu[p0 + ar1],      fkey(m2));
        atomicMax(&g_maxu[p0 + ar1 + 8],  fkey(m3));
    }
}

// ============================================================
// Kernel 4: PASS 2 — same sweep (identical approx values), emit
// candidates >= max - MARGIN (final global max -> few cands/pt)
// ============================================================
__global__ void __launch_bounds__(THREADS)
pass2_kernel() {
    __shared__ __align__(16) unsigned short sZ[PTS_PER_BLOCK * SROW];
    __shared__ __align__(16) unsigned short sC[TILE_C * SROW];

    const int tid  = threadIdx.x;
    const int w    = tid >> 5;
    const int lane = tid & 31;
    const int qr   = lane >> 2;
    const int qc   = (lane & 3) * 2;

    const unsigned int sc0 =
        smem_u32(sC) + ((lane & 7) * SROW + (lane >> 3) * 8) * 2;

    const int it = blockIdx.x;
    const int pg = it >> 3;
    const int cr = it & 7;
    const int p0 = pg * PTS_PER_BLOCK;
    const int c0r = cr * CODES_PER_RANGE;

    fill_tile(sZ, g_znh + p0 * DIM, PTS_PER_BLOCK, tid);
    __syncthreads();

    const int ar0 = w * 32 + qr;
    const int ar1 = ar0 + 16;
    const int pt0 = p0 + ar0;
    const int pt1 = p0 + ar1;
    unsigned int A0[4], A1[4], A2[4], A3[4];
    load_A(sZ, ar0, qc, A0, A1);
    load_A(sZ, ar1, qc, A2, A3);

    const float th0 = finv(g_maxu[pt0])     - MARGIN;
    const float th1 = finv(g_maxu[pt0 + 8]) - MARGIN;
    const float th2 = finv(g_maxu[pt1])     - MARGIN;
    const float th3 = finv(g_maxu[pt1 + 8]) - MARGIN;

    for (int t = 0; t < CODES_PER_RANGE; t += TILE_C) {
        __syncthreads();
        fill_tile(sC, g_ewh + (c0r + t) * DIM, TILE_C, tid);
        __syncthreads();

#pragma unroll 4
        for (int nt = 0; nt < TILE_C / 8; nt++) {
            unsigned int B[4];
            ldsm_x4(B, sc0 + nt * (8 * SROW * 2));
            float ca[4] = {0.f, 0.f, 0.f, 0.f};
            float cb[4] = {0.f, 0.f, 0.f, 0.f};
            float cc[4] = {0.f, 0.f, 0.f, 0.f};
            float cd[4] = {0.f, 0.f, 0.f, 0.f};
            hmma(ca, A0, B);
            hmma(cb, A1, B + 2);
            hmma(cc, A2, B);
            hmma(cd, A3, B + 2);
            const float d00 = ca[0] + cb[0], d01 = ca[1] + cb[1];
            const float d02 = ca[2] + cb[2], d03 = ca[3] + cb[3];
            const float d10 = cc[0] + cd[0], d11 = cc[1] + cd[1];
            const float d12 = cc[2] + cd[2], d13 = cc[3] + cd[3];

            if ((d00 >= th0) | (d01 >= th0) | (d02 >= th1) | (d03 >= th1) |
                (d10 >= th2) | (d11 >= th2) | (d12 >= th3) | (d13 >= th3)) {
                const int code0 = c0r + t + nt * 8 + qc;
                if (d00 >= th0) push_cand(pt0,     code0);
                if (d01 >= th0) push_cand(pt0,     code0 + 1);
                if (d02 >= th1) push_cand(pt0 + 8, code0);
                if (d03 >= th1) push_cand(pt0 + 8, code0 + 1);
                if (d10 >= th2) push_cand(pt1,     code0);
                if (d11 >= th2) push_cand(pt1,     code0 + 1);
                if (d12 >= th3) push_cand(pt1 + 8, code0);
                if (d13 >= th3) push_cand(pt1 + 8, code0 + 1);
            }
        }
    }
}

// ============================================================
// Kernel 5: exact fp32 rescore of candidates, atomicMax merge
// chain order (d mod 4, (S0+S2)+(S1+S3)) -> bit-identical dots
// ============================================================
__global__ void rescore_kernel() {
    const unsigned int n = g_ncand;
    const unsigned int lim = n < CAP ? n : CAP;
    for (unsigned int i = blockIdx.x * blockDim.x + threadIdx.x; i < lim;
         i += gridDim.x * blockDim.x) {
        const unsigned int e = g_cand[i];
        const int pt = e >> 13;
        const int k  = e & 8191;
        const float4* zp = reinterpret_cast<const float4*>(g_zn + pt * DIM);
        const float4* cp = reinterpret_cast<const float4*>(g_ew + k * DIM);
        float4 zv = zp[0], cv = cp[0];
        float s0 = zv.x * cv.x, s1 = zv.y * cv.y;
        float s2 = zv.z * cv.z, s3 = zv.w * cv.w;
#pragma unroll
        for (int h = 1; h < 8; h++) {
            zv = zp[h]; cv = cp[h];
            s0 = fmaf(zv.x, cv.x, s0);
            s1 = fmaf(zv.y, cv.y, s1);
            s2 = fmaf(zv.z, cv.z, s2);
            s3 = fmaf(zv.w, cv.w, s3);
        }
        const float dot = (s0 + s2) + (s1 + s3);
        unsigned long long pk =
            ((unsigned long long)fkey(dot) << 32) | (unsigned)(8191 - k);
        atomicMax(&g_bestpk[pt], pk);
    }
}

// ============================================================
// Kernel 6: finalize — idx + z_q (bchw) + histogram + loss partials
// ============================================================
__global__ void __launch_bounds__(THREADS)
finalize_kernel(float* __restrict__ out) {
    const int n = blockIdx.x * THREADS + threadIdx.x;

    const unsigned long long pk = g_bestpk[n];
    const int bi = 8191 - (int)(pk & 0xFFFFFFFFull);
    const float best = finv((unsigned int)(pk >> 32));

    out[N_PTS * DIM + 2 + n] = (float)bi;
    atomicAdd(&g_hist[bi], 1);

    const float4* ep = reinterpret_cast<const float4*>(g_ew + bi * DIM);
    const int b  = n >> 10;
    const int hw = n & 1023;
    float* op = out + b * (DIM * 1024) + hw;
#pragma unroll
    for (int i = 0; i < 8; i++) {
        float4 e = ep[i];
        op[(4 * i + 0) * 1024] = e.x;
        op[(4 * i + 1) * 1024] = e.y;
        op[(4 * i + 2) * 1024] = e.z;
        op[(4 * i + 3) * 1024] = e.w;
    }

    __shared__ float red[THREADS];
    red[threadIdx.x] = 2.0f - 2.0f * best;
    __syncthreads();
#pragma unroll
    for (int st = THREADS / 2; st > 0; st >>= 1) {
        if (threadIdx.x < st) red[threadIdx.x] += red[threadIdx.x + st];
        __syncthreads();
    }
    if (threadIdx.x == 0) g_part[blockIdx.x] = red[0];
}

// ============================================================
// Kernel 7: entropy partials
// ============================================================
__global__ void ent_kernel() {
    const int bin = blockIdx.x * 256 + threadIdx.x;
    const float denom = (float)N_PTS + (float)K_EMB * 1e-4f;
    const float invd  = 1.0f / denom;
    float p = ((float)g_hist[bin] + 1e-4f) * invd;
    __shared__ float sh[256];
    sh[threadIdx.x] = p * logf(p);
    __syncthreads();
#pragma unroll
    for (int st = 128; st > 0; st >>= 1) {
        if (threadIdx.x < st) sh[threadIdx.x] += sh[threadIdx.x + st];
        __syncthreads();
    }
    if (threadIdx.x == 0) g_entp[blockIdx.x] = sh[0];
}

// ============================================================
// Kernel 8: final scalars
// ============================================================
__global__ void scalars_kernel(float* __restrict__ out) {
    const int t = threadIdx.x;
    __shared__ float sh[THREADS];

    sh[t] = (t < 32) ? g_entp[t] : 0.f;
    __syncthreads();
#pragma unroll
    for (int st = THREADS / 2; st > 0; st >>= 1) {
        if (t < st) sh[t] += sh[t + st];
        __syncthreads();
    }
    float entropy = -sh[0];
    __syncthreads();

    sh[t] = (t < NBLK) ? g_part[t] : 0.f;
    __syncthreads();
#pragma unroll
    for (int st = THREADS / 2; st > 0; st >>= 1) {
        if (t < st) sh[t] += sh[t + st];
        __syncthreads();
    }
    if (t == 0) {
        out[N_PTS * DIM + 0] = 1.25f * (sh[0] / (float)N_PTS);
        out[N_PTS * DIM + 1] = entropy;
    }
}

// ============================================================
extern "C" void kernel_launch(void* const* d_in, const int* in_sizes, int n_in,
                              void* d_out, int out_size) {
    const float* z   = (const float*)d_in[0];
    const float* emb = (const float*)d_in[1];
    if (n_in >= 2 && in_sizes[0] == K_EMB * DIM && in_sizes[1] == N_PTS * DIM) {
        z   = (const float*)d_in[1];
        emb = (const float*)d_in[0];
    }
    float* out = (float*)d_out;

    init_kernel<<<N_PTS / THREADS, THREADS>>>();        // 1
    prep_emb<<<K_EMB / THREADS, THREADS>>>(emb);        // 2
    prep_z<<<N_PTS / THREADS, THREADS>>>(z);            // 3
    pass1_kernel<<<ITEMS, THREADS>>>();                 // 4 (profiled)
    pass2_kernel<<<ITEMS, THREADS>>>();                 // 5
    rescore_kernel<<<1024, THREADS>>>();                // 6
    finalize_kernel<<<NBLK, THREADS>>>(out);            // 7
    ent_kernel<<<32, 256>>>();                          // 8
    scalars_kernel<<<1, THREADS>>>(out);                // 9
}

// round 14
// speedup vs baseline: 1.1234x; 1.1234x over previous
#include <cuda_runtime.h>
#include <cuda_bf16.h>
#include <math.h>

#define N_PTS   32768
#define K_EMB   8192
#define DIM     32
#define THREADS 256
#define NBLK    (N_PTS / THREADS)        // 128
#define PTS_PER_BLOCK 256                // 8 warps * 32 pts (2 A-tiles each)
#define PTGRPS  (N_PTS / PTS_PER_BLOCK)  // 128
#define CRANGES 4
#define CODES_PER_RANGE (K_EMB / CRANGES)   // 2048
#define TILE_C  128                       // codes per smem tile (double-buffered)
#define NTILES  (CODES_PER_RANGE / TILE_C)  // 16
#define ITEMS   (PTGRPS * CRANGES)        // 512
#define SROW    40                        // padded bf16 row stride
#define MARGIN  0.04f
#define CAP     (1u << 23)                // 8M candidate slots

// ---- scratch (device globals; no allocation allowed) ----
__device__ float          g_ew [K_EMB * DIM];    // normalized codes fp32
__device__ unsigned short g_ewh[K_EMB * DIM];    // normalized codes bf16 bits
__device__ float          g_zn [N_PTS * DIM];    // normalized points fp32
__device__ unsigned short g_znh[N_PTS * DIM];    // normalized points bf16 bits
__device__ unsigned int   g_maxu[N_PTS];         // sortable max approx dot
__device__ unsigned long long g_bestpk[N_PTS];   // packed (key(dot)<<32)|(8191-idx)
__device__ unsigned int   g_ncand;
__device__ unsigned int   g_cand[CAP];           // (pt<<13)|code
__device__ int   g_hist[K_EMB];
__device__ float g_part[NBLK];
__device__ float g_entp[32];

// ---- sortable float <-> u32 ----
__device__ __forceinline__ unsigned int fkey(float f) {
    unsigned int s = __float_as_uint(f);
    return (s & 0x80000000u) ? ~s : (s | 0x80000000u);
}
__device__ __forceinline__ float finv(unsigned int k) {
    unsigned int s = (k & 0x80000000u) ? (k ^ 0x80000000u) : ~k;
    return __uint_as_float(s);
}

// ---- m16n8k16 bf16 MMA, fp32 accum ----
__device__ __forceinline__ void hmma(float* c, const unsigned int* a,
                                     const unsigned int* b) {
    asm volatile(
        "mma.sync.aligned.m16n8k16.row.col.f32.bf16.bf16.f32 "
        "{%0,%1,%2,%3}, {%4,%5,%6,%7}, {%8,%9}, {%0,%1,%2,%3};"
        : "+f"(c[0]), "+f"(c[1]), "+f"(c[2]), "+f"(c[3])
        : "r"(a[0]), "r"(a[1]), "r"(a[2]), "r"(a[3]),
          "r"(b[0]), "r"(b[1]));
}

// ---- ldmatrix x4: all four B fragments in one LDSM (layout proven R10) ----
__device__ __forceinline__ void ldsm_x4(unsigned int* r, unsigned int addr) {
    asm volatile(
        "ldmatrix.sync.aligned.m8n8.x4.shared.b16 {%0,%1,%2,%3}, [%4];"
        : "=r"(r[0]), "=r"(r[1]), "=r"(r[2]), "=r"(r[3]) : "r"(addr));
}

__device__ __forceinline__ unsigned int smem_u32(const void* p) {
    return (unsigned int)__cvta_generic_to_shared(p);
}

// ---- candidate push (only past-threshold; ~few per point) ----
__device__ __forceinline__ void push_cand(int pt, int code) {
    unsigned int p = atomicAdd(&g_ncand, 1u);
    if (p < CAP)
        g_cand[p] = ((unsigned)pt << 13) | (unsigned)code;
}

// ============================================================
// Kernel 0: init scratch   (launch #1)
// ============================================================
__global__ void init_kernel() {
    int i = blockIdx.x * blockDim.x + threadIdx.x;   // 0..32767
    if (i < K_EMB) g_hist[i] = 0;
    g_maxu[i] = 0u;
    g_bestpk[i] = 0ull;
    if (i == 0) g_ncand = 0u;
}

// ============================================================
// Kernel 1: normalize embedding rows -> fp32 + bf16
// ============================================================
__global__ void prep_emb(const float* __restrict__ emb) {
    int r = blockIdx.x * blockDim.x + threadIdx.x;   // 0..8191

    const float4* src = reinterpret_cast<const float4*>(emb + r * DIM);
    float4 v[8];
    float s = 0.f;
#pragma unroll
    for (int i = 0; i < 8; i++) {
        v[i] = src[i];
        s += v[i].x * v[i].x + v[i].y * v[i].y + v[i].z * v[i].z + v[i].w * v[i].w;
    }
    float inv = 1.0f / fmaxf(sqrtf(s), 1e-12f);
    float4* dst = reinterpret_cast<float4*>(g_ew + r * DIM);
#pragma unroll
    for (int i = 0; i < 8; i++) {
        float4 o;
        o.x = v[i].x * inv; o.y = v[i].y * inv;
        o.z = v[i].z * inv; o.w = v[i].w * inv;
        dst[i] = o;
        g_ewh[r * DIM + 4 * i + 0] = __bfloat16_as_ushort(__float2bfloat16(o.x));
        g_ewh[r * DIM + 4 * i + 1] = __bfloat16_as_ushort(__float2bfloat16(o.y));
        g_ewh[r * DIM + 4 * i + 2] = __bfloat16_as_ushort(__float2bfloat16(o.z));
        g_ewh[r * DIM + 4 * i + 3] = __bfloat16_as_ushort(__float2bfloat16(o.w));
    }
}

// ============================================================
// Kernel 2: normalize points (bchw gather) -> fp32 + bf16
// ============================================================
__global__ void prep_z(const float* __restrict__ z) {
    int n = blockIdx.x * blockDim.x + threadIdx.x;   // 0..32767
    const int b  = n >> 10;
    const int hw = n & 1023;
    const float* zp = z + b * (DIM * 1024) + hw;
    float zn[DIM];
    float s = 0.f;
#pragma unroll
    for (int d = 0; d < DIM; d++) {
        float v = zp[d * 1024];
        zn[d] = v;
        s += v * v;
    }
    float inv = 1.0f / fmaxf(sqrtf(s), 1e-12f);
#pragma unroll
    for (int d = 0; d < DIM; d++) {
        float t = zn[d] * inv;
        g_zn [n * DIM + d] = t;
        g_znh[n * DIM + d] = __bfloat16_as_ushort(__float2bfloat16(t));
    }
}

// ---- sZ fill: uint4 chunks (row = 64B payload = 4 chunks) ----
__device__ __forceinline__ void fill_z(unsigned short* dst,
                                       const unsigned short* src, int tid) {
    const uint4* s = reinterpret_cast<const uint4*>(src);
#pragma unroll
    for (int i = 0; i < (PTS_PER_BLOCK * 4) / THREADS; i++) {
        int idx = tid + i * THREADS;
        int r = idx >> 2, c = idx & 3;
        *reinterpret_cast<uint4*>(&dst[r * SROW + c * 8]) = s[idx];
    }
}

// ---- cp.async prefetch of one code tile (TILE_C rows, 16B chunks) ----
__device__ __forceinline__ void prefetch_tile(unsigned int dst_s,
                                              const unsigned short* src,
                                              int tid) {
#pragma unroll
    for (int i = 0; i < (TILE_C * 4) / THREADS; i++) {   // 2 per thread
        int idx = tid + i * THREADS;
        int r = idx >> 2, c = idx & 3;
        unsigned int d = dst_s + r * (SROW * 2) + c * 16;
        const void* g = src + r * DIM + c * 8;
        asm volatile("cp.async.cg.shared.global [%0], [%1], 16;"
                     :: "r"(d), "l"(g) : "memory");
    }
    asm volatile("cp.async.commit_group;" ::: "memory");
}
__device__ __forceinline__ void cp_wait0() {
    asm volatile("cp.async.wait_group 0;" ::: "memory");
}

// ---- load the two k-half A fragments for one m16 tile (proven layout) ----
__device__ __forceinline__ void load_A(const unsigned short* sZ, int row,
                                       int qc, unsigned int* A0,
                                       unsigned int* A1) {
    A0[0] = *reinterpret_cast<const unsigned int*>(&sZ[row * SROW + qc]);
    A0[1] = *reinterpret_cast<const unsigned int*>(&sZ[(row + 8) * SROW + qc]);
    A0[2] = *reinterpret_cast<const unsigned int*>(&sZ[row * SROW + qc + 8]);
    A0[3] = *reinterpret_cast<const unsigned int*>(&sZ[(row + 8) * SROW + qc + 8]);
    A1[0] = *reinterpret_cast<const unsigned int*>(&sZ[row * SROW + qc + 16]);
    A1[1] = *reinterpret_cast<const unsigned int*>(&sZ[(row + 8) * SROW + qc + 16]);
    A1[2] = *reinterpret_cast<const unsigned int*>(&sZ[row * SROW + qc + 24]);
    A1[3] = *reinterpret_cast<const unsigned int*>(&sZ[(row + 8) * SROW + qc + 24]);
}

// ============================================================
// Kernel 3: PASS 1 — bf16 MMA sweep, per-point max approx dot
// R12 math (serial accumulators) + cp.async double-buffered tiles
// (launch #4 -> profiled)
// ============================================================
__global__ void __launch_bounds__(THREADS)
pass1_kernel() {
    __shared__ __align__(16) unsigned short sZ[PTS_PER_BLOCK * SROW];   // 20 KB
    __shared__ __align__(16) unsigned short sC[2][TILE_C * SROW];       // 2x10 KB

    const int tid  = threadIdx.x;
    const int w    = tid >> 5;
    const int lane = tid & 31;
    const int qr   = lane >> 2;          // 0..7
    const int qc   = (lane & 3) * 2;     // 0,2,4,6

    const unsigned int lds_off = ((lane & 7) * SROW + (lane >> 3) * 8) * 2;
    const unsigned int scbase0 = smem_u32(sC[0]);
    const unsigned int scbase1 = smem_u32(sC[1]);

    const int it = blockIdx.x;              // one item per block
    const int pg = it >> 2;                 // point group 0..127
    const int cr = it & 3;                  // code range 0..3
    const int p0 = pg * PTS_PER_BLOCK;
    const int c0r = cr * CODES_PER_RANGE;

    fill_z(sZ, g_znh + p0 * DIM, tid);
    prefetch_tile(scbase0, g_ewh + c0r * DIM, tid);
    __syncthreads();

    // two A tiles per warp: rows w*32 .. w*32+31
    const int ar0 = w * 32 + qr;
    const int ar1 = ar0 + 16;
    unsigned int A0[4], A1[4], A2[4], A3[4];
    load_A(sZ, ar0, qc, A0, A1);
    load_A(sZ, ar1, qc, A2, A3);

    float m0 = -2.0f, m1 = -2.0f, m2 = -2.0f, m3 = -2.0f;

    for (int t = 0; t < NTILES; t++) {
        cp_wait0();
        __syncthreads();
        if (t + 1 < NTILES)
            prefetch_tile((t & 1) ? scbase0 : scbase1,
                          g_ewh + (c0r + (t + 1) * TILE_C) * DIM, tid);
        const unsigned int sc0 = ((t & 1) ? scbase1 : scbase0) + lds_off;

#pragma unroll 4
        for (int nt = 0; nt < TILE_C / 8; nt++) {
            unsigned int B[4];
            ldsm_x4(B, sc0 + nt * (8 * SROW * 2));   // all 4 B frags
            float c0[4] = {0.f, 0.f, 0.f, 0.f};
            float c1[4] = {0.f, 0.f, 0.f, 0.f};
            hmma(c0, A0, B);
            hmma(c0, A1, B + 2);
            hmma(c1, A2, B);
            hmma(c1, A3, B + 2);
            m0 = fmaxf(m0, fmaxf(c0[0], c0[1]));
            m1 = fmaxf(m1, fmaxf(c0[2], c0[3]));
            m2 = fmaxf(m2, fmaxf(c1[0], c1[1]));
            m3 = fmaxf(m3, fmaxf(c1[2], c1[3]));
        }
    }
    // reduce max over the 4 threads of each quad (cols)
#pragma unroll
    for (int x = 1; x < 4; x <<= 1) {
        m0 = fmaxf(m0, __shfl_xor_sync(0xFFFFFFFFu, m0, x));
        m1 = fmaxf(m1, __shfl_xor_sync(0xFFFFFFFFu, m1, x));
        m2 = fmaxf(m2, __shfl_xor_sync(0xFFFFFFFFu, m2, x));
        m3 = fmaxf(m3, __shfl_xor_sync(0xFFFFFFFFu, m3, x));
    }
    if ((lane & 3) == 0) {
        atomicMax(&g_maxu[p0 + ar0],      fkey(m0));
        atomicMax(&g_maxu[p0 + ar0 + 8],  fkey(m1));
        atomicMax(&g_maxu[p0 + ar1],      fkey(m2));
        atomicMax(&g_maxu[p0 + ar1 + 8],  fkey(m3));
    }
}

// ============================================================
// Kernel 4: PASS 2 — same sweep (identical approx values), emit
// candidates >= max - MARGIN (final global max -> few cands/pt)
// ============================================================
__global__ void __launch_bounds__(THREADS)
pass2_kernel() {
    __shared__ __align__(16) unsigned short sZ[PTS_PER_BLOCK * SROW];
    __shared__ __align__(16) unsigned short sC[2][TILE_C * SROW];

    const int tid  = threadIdx.x;
    const int w    = tid >> 5;
    const int lane = tid & 31;
    const int qr   = lane >> 2;
    const int qc   = (lane & 3) * 2;

    const unsigned int lds_off = ((lane & 7) * SROW + (lane >> 3) * 8) * 2;
    const unsigned int scbase0 = smem_u32(sC[0]);
    const unsigned int scbase1 = smem_u32(sC[1]);

    const int it = blockIdx.x;
    const int pg = it >> 2;
    const int cr = it & 3;
    const int p0 = pg * PTS_PER_BLOCK;
    const int c0r = cr * CODES_PER_RANGE;

    fill_z(sZ, g_znh + p0 * DIM, tid);
    prefetch_tile(scbase0, g_ewh + c0r * DIM, tid);
    __syncthreads();

    const int ar0 = w * 32 + qr;
    const int ar1 = ar0 + 16;
    const int pt0 = p0 + ar0;
    const int pt1 = p0 + ar1;
    unsigned int A0[4], A1[4], A2[4], A3[4];
    load_A(sZ, ar0, qc, A0, A1);
    load_A(sZ, ar1, qc, A2, A3);

    const float th0 = finv(g_maxu[pt0])     - MARGIN;
    const float th1 = finv(g_maxu[pt0 + 8]) - MARGIN;
    const float th2 = finv(g_maxu[pt1])     - MARGIN;
    const float th3 = finv(g_maxu[pt1 + 8]) - MARGIN;

    for (int t = 0; t < NTILES; t++) {
        cp_wait0();
        __syncthreads();
        if (t + 1 < NTILES)
            prefetch_tile((t & 1) ? scbase0 : scbase1,
                          g_ewh + (c0r + (t + 1) * TILE_C) * DIM, tid);
        const unsigned int sc0 = ((t & 1) ? scbase1 : scbase0) + lds_off;

#pragma unroll 4
        for (int nt = 0; nt < TILE_C / 8; nt++) {
            unsigned int B[4];
            ldsm_x4(B, sc0 + nt * (8 * SROW * 2));
            float c0[4] = {0.f, 0.f, 0.f, 0.f};
            float c1[4] = {0.f, 0.f, 0.f, 0.f};
            hmma(c0, A0, B);
            hmma(c0, A1, B + 2);
            hmma(c1, A2, B);
            hmma(c1, A3, B + 2);

            if ((c0[0] >= th0) | (c0[1] >= th0) | (c0[2] >= th1) | (c0[3] >= th1) |
                (c1[0] >= th2) | (c1[1] >= th2) | (c1[2] >= th3) | (c1[3] >= th3)) {
                const int code0 = c0r + t * TILE_C + nt * 8 + qc;
                if (c0[0] >= th0) push_cand(pt0,     code0);
                if (c0[1] >= th0) push_cand(pt0,     code0 + 1);
                if (c0[2] >= th1) push_cand(pt0 + 8, code0);
                if (c0[3] >= th1) push_cand(pt0 + 8, code0 + 1);
                if (c1[0] >= th2) push_cand(pt1,     code0);
                if (c1[1] >= th2) push_cand(pt1,     code0 + 1);
                if (c1[2] >= th3) push_cand(pt1 + 8, code0);
                if (c1[3] >= th3) push_cand(pt1 + 8, code0 + 1);
            }
        }
    }
}

// ============================================================
// Kernel 5: exact fp32 rescore of candidates, atomicMax merge
// chain order (d mod 4, (S0+S2)+(S1+S3)) -> bit-identical dots
// ============================================================
__global__ void rescore_kernel() {
    const unsigned int n = g_ncand;
    const unsigned int lim = n < CAP ? n : CAP;
    for (unsigned int i = blockIdx.x * blockDim.x + threadIdx.x; i < lim;
         i += gridDim.x * blockDim.x) {
        const unsigned int e = g_cand[i];
        const int pt = e >> 13;
        const int k  = e & 8191;
        const float4* zp = reinterpret_cast<const float4*>(g_zn + pt * DIM);
        const float4* cp = reinterpret_cast<const float4*>(g_ew + k * DIM);
        float4 zv = zp[0], cv = cp[0];
        float s0 = zv.x * cv.x, s1 = zv.y * cv.y;
        float s2 = zv.z * cv.z, s3 = zv.w * cv.w;
#pragma unroll
        for (int h = 1; h < 8; h++) {
            zv = zp[h]; cv = cp[h];
            s0 = fmaf(zv.x, cv.x, s0);
            s1 = fmaf(zv.y, cv.y, s1);
            s2 = fmaf(zv.z, cv.z, s2);
            s3 = fmaf(zv.w, cv.w, s3);
        }
        const float dot = (s0 + s2) + (s1 + s3);
        unsigned long long pk =
            ((unsigned long long)fkey(dot) << 32) | (unsigned)(8191 - k);
        atomicMax(&g_bestpk[pt], pk);
    }
}

// ============================================================
// Kernel 6: finalize — idx + z_q (bchw) + histogram + loss partials
// ============================================================
__global__ void __launch_bounds__(THREADS)
finalize_kernel(float* __restrict__ out) {
    const int n = blockIdx.x * THREADS + threadIdx.x;

    const unsigned long long pk = g_bestpk[n];
    const int bi = 8191 - (int)(pk & 0xFFFFFFFFull);
    const float best = finv((unsigned int)(pk >> 32));

    out[N_PTS * DIM + 2 + n] = (float)bi;
    atomicAdd(&g_hist[bi], 1);

    const float4* ep = reinterpret_cast<const float4*>(g_ew + bi * DIM);
    const int b  = n >> 10;
    const int hw = n & 1023;
    float* op = out + b * (DIM * 1024) + hw;
#pragma unroll
    for (int i = 0; i < 8; i++) {
        float4 e = ep[i];
        op[(4 * i + 0) * 1024] = e.x;
        op[(4 * i + 1) * 1024] = e.y;
        op[(4 * i + 2) * 1024] = e.z;
        op[(4 * i + 3) * 1024] = e.w;
    }

    __shared__ float red[THREADS];
    red[threadIdx.x] = 2.0f - 2.0f * best;
    __syncthreads();
#pragma unroll
    for (int st = THREADS / 2; st > 0; st >>= 1) {
        if (threadIdx.x < st) red[threadIdx.x] += red[threadIdx.x + st];
        __syncthreads();
    }
    if (threadIdx.x == 0) g_part[blockIdx.x] = red[0];
}

// ============================================================
// Kernel 7: entropy partials
// ============================================================
__global__ void ent_kernel() {
    const int bin = blockIdx.x * 256 + threadIdx.x;
    const float denom = (float)N_PTS + (float)K_EMB * 1e-4f;
    const float invd  = 1.0f / denom;
    float p = ((float)g_hist[bin] + 1e-4f) * invd;
    __shared__ float sh[256];
    sh[threadIdx.x] = p * logf(p);
    __syncthreads();
#pragma unroll
    for (int st = 128; st > 0; st >>= 1) {
        if (threadIdx.x < st) sh[threadIdx.x] += sh[threadIdx.x + st];
        __syncthreads();
    }
    if (threadIdx.x == 0) g_entp[blockIdx.x] = sh[0];
}

// ============================================================
// Kernel 8: final scalars
// ============================================================
__global__ void scalars_kernel(float* __restrict__ out) {
    const int t = threadIdx.x;
    __shared__ float sh[THREADS];

    sh[t] = (t < 32) ? g_entp[t] : 0.f;
    __syncthreads();
#pragma unroll
    for (int st = THREADS / 2; st > 0; st >>= 1) {
        if (t < st) sh[t] += sh[t + st];
        __syncthreads();
    }
    float entropy = -sh[0];
    __syncthreads();

    sh[t] = (t < NBLK) ? g_part[t] : 0.f;
    __syncthreads();
#pragma unroll
    for (int st = THREADS / 2; st > 0; st >>= 1) {
        if (t < st) sh[t] += sh[t + st];
        __syncthreads();
    }
    if (t == 0) {
        out[N_PTS * DIM + 0] = 1.25f * (sh[0] / (float)N_PTS);
        out[N_PTS * DIM + 1] = entropy;
    }
}

// ============================================================
extern "C" void kernel_launch(void* const* d_in, const int* in_sizes, int n_in,
                              void* d_out, int out_size) {
    const float* z   = (const float*)d_in[0];
    const float* emb = (const float*)d_in[1];
    if (n_in >= 2 && in_sizes[0] == K_EMB * DIM && in_sizes[1] == N_PTS * DIM) {
        z   = (const float*)d_in[1];
        emb = (const float*)d_in[0];
    }
    float* out = (float*)d_out;

    init_kernel<<<N_PTS / THREADS, THREADS>>>();        // 1
    prep_emb<<<K_EMB / THREADS, THREADS>>>(emb);        // 2
    prep_z<<<N_PTS / THREADS, THREADS>>>(z);            // 3
    pass1_kernel<<<ITEMS, THREADS>>>();                 // 4 (profiled)
    pass2_kernel<<<ITEMS, THREADS>>>();                 // 5
    rescore_kernel<<<1024, THREADS>>>();                // 6
    finalize_kernel<<<NBLK, THREADS>>>(out);            // 7
    ent_kernel<<<32, 256>>>();                          // 8
    scalars_kernel<<<1, THREADS>>>(out);                // 9
}

// round 15
// speedup vs baseline: 1.1387x; 1.0136x over previous
#include <cuda_runtime.h>
#include <cuda_bf16.h>
#include <math.h>

#define N_PTS   32768
#define K_EMB   8192
#define DIM     32
#define THREADS 256
#define NBLK    (N_PTS / THREADS)        // 128
#define PTS_PER_BLOCK 256                // 8 warps * 32 pts (2 A-tiles each)
#define PTGRPS  (N_PTS / PTS_PER_BLOCK)  // 128
#define CRANGES 8
#define CODES_PER_RANGE (K_EMB / CRANGES)   // 1024
#define TILE_C  128                       // codes per smem tile (double-buffered)
#define NTILES  (CODES_PER_RANGE / TILE_C)  // 8
#define ITEMS   (PTGRPS * CRANGES)        // 1024 -> ~5 resident blocks/SM
#define SROW    40                        // padded bf16 row stride
#define MARGIN  0.04f
#define CAP     (1u << 23)                // 8M candidate slots

// ---- scratch (device globals; no allocation allowed) ----
__device__ float          g_ew [K_EMB * DIM];    // normalized codes fp32
__device__ unsigned short g_ewh[K_EMB * DIM];    // normalized codes bf16 bits
__device__ float          g_zn [N_PTS * DIM];    // normalized points fp32
__device__ unsigned short g_znh[N_PTS * DIM];    // normalized points bf16 bits
__device__ unsigned int   g_maxu[N_PTS];         // sortable max approx dot
__device__ unsigned long long g_bestpk[N_PTS];   // packed (key(dot)<<32)|(8191-idx)
__device__ unsigned int   g_ncand;
__device__ unsigned int   g_cand[CAP];           // (pt<<13)|code
__device__ int   g_hist[K_EMB];
__device__ float g_part[NBLK];
__device__ float g_entp[32];

// ---- sortable float <-> u32 ----
__device__ __forceinline__ unsigned int fkey(float f) {
    unsigned int s = __float_as_uint(f);
    return (s & 0x80000000u) ? ~s : (s | 0x80000000u);
}
__device__ __forceinline__ float finv(unsigned int k) {
    unsigned int s = (k & 0x80000000u) ? (k ^ 0x80000000u) : ~k;
    return __uint_as_float(s);
}

// ---- m16n8k16 bf16 MMA, fp32 accum ----
__device__ __forceinline__ void hmma(float* c, const unsigned int* a,
                                     const unsigned int* b) {
    asm volatile(
        "mma.sync.aligned.m16n8k16.row.col.f32.bf16.bf16.f32 "
        "{%0,%1,%2,%3}, {%4,%5,%6,%7}, {%8,%9}, {%0,%1,%2,%3};"
        : "+f"(c[0]), "+f"(c[1]), "+f"(c[2]), "+f"(c[3])
        : "r"(a[0]), "r"(a[1]), "r"(a[2]), "r"(a[3]),
          "r"(b[0]), "r"(b[1]));
}

// ---- ldmatrix x4: all four B fragments in one LDSM (layout proven R10) ----
__device__ __forceinline__ void ldsm_x4(unsigned int* r, unsigned int addr) {
    asm volatile(
        "ldmatrix.sync.aligned.m8n8.x4.shared.b16 {%0,%1,%2,%3}, [%4];"
        : "=r"(r[0]), "=r"(r[1]), "=r"(r[2]), "=r"(r[3]) : "r"(addr));
}

__device__ __forceinline__ unsigned int smem_u32(const void* p) {
    return (unsigned int)__cvta_generic_to_shared(p);
}

// ---- candidate push (only past-threshold; ~few per point) ----
__device__ __forceinline__ void push_cand(int pt, int code) {
    unsigned int p = atomicAdd(&g_ncand, 1u);
    if (p < CAP)
        g_cand[p] = ((unsigned)pt << 13) | (unsigned)code;
}

// ============================================================
// Kernel 0: init scratch   (launch #1)
// ============================================================
__global__ void init_kernel() {
    int i = blockIdx.x * blockDim.x + threadIdx.x;   // 0..32767
    if (i < K_EMB) g_hist[i] = 0;
    g_maxu[i] = 0u;
    g_bestpk[i] = 0ull;
    if (i == 0) g_ncand = 0u;
}

// ============================================================
// Kernel 1: normalize embedding rows -> fp32 + bf16
// ============================================================
__global__ void prep_emb(const float* __restrict__ emb) {
    int r = blockIdx.x * blockDim.x + threadIdx.x;   // 0..8191

    const float4* src = reinterpret_cast<const float4*>(emb + r * DIM);
    float4 v[8];
    float s = 0.f;
#pragma unroll
    for (int i = 0; i < 8; i++) {
        v[i] = src[i];
        s += v[i].x * v[i].x + v[i].y * v[i].y + v[i].z * v[i].z + v[i].w * v[i].w;
    }
    float inv = 1.0f / fmaxf(sqrtf(s), 1e-12f);
    float4* dst = reinterpret_cast<float4*>(g_ew + r * DIM);
#pragma unroll
    for (int i = 0; i < 8; i++) {
        float4 o;
        o.x = v[i].x * inv; o.y = v[i].y * inv;
        o.z = v[i].z * inv; o.w = v[i].w * inv;
        dst[i] = o;
        g_ewh[r * DIM + 4 * i + 0] = __bfloat16_as_ushort(__float2bfloat16(o.x));
        g_ewh[r * DIM + 4 * i + 1] = __bfloat16_as_ushort(__float2bfloat16(o.y));
        g_ewh[r * DIM + 4 * i + 2] = __bfloat16_as_ushort(__float2bfloat16(o.z));
        g_ewh[r * DIM + 4 * i + 3] = __bfloat16_as_ushort(__float2bfloat16(o.w));
    }
}

// ============================================================
// Kernel 2: normalize points (bchw gather) -> fp32 + bf16
// ============================================================
__global__ void prep_z(const float* __restrict__ z) {
    int n = blockIdx.x * blockDim.x + threadIdx.x;   // 0..32767
    const int b  = n >> 10;
    const int hw = n & 1023;
    const float* zp = z + b * (DIM * 1024) + hw;
    float zn[DIM];
    float s = 0.f;
#pragma unroll
    for (int d = 0; d < DIM; d++) {
        float v = zp[d * 1024];
        zn[d] = v;
        s += v * v;
    }
    float inv = 1.0f / fmaxf(sqrtf(s), 1e-12f);
#pragma unroll
    for (int d = 0; d < DIM; d++) {
        float t = zn[d] * inv;
        g_zn [n * DIM + d] = t;
        g_znh[n * DIM + d] = __bfloat16_as_ushort(__float2bfloat16(t));
    }
}

// ---- sZ fill: uint4 chunks (row = 64B payload = 4 chunks) ----
__device__ __forceinline__ void fill_z(unsigned short* dst,
                                       const unsigned short* src, int tid) {
    const uint4* s = reinterpret_cast<const uint4*>(src);
#pragma unroll
    for (int i = 0; i < (PTS_PER_BLOCK * 4) / THREADS; i++) {
        int idx = tid + i * THREADS;
        int r = idx >> 2, c = idx & 3;
        *reinterpret_cast<uint4*>(&dst[r * SROW + c * 8]) = s[idx];
    }
}

// ---- cp.async prefetch of one code tile (TILE_C rows, 16B chunks) ----
__device__ __forceinline__ void prefetch_tile(unsigned int dst_s,
                                              const unsigned short* src,
                                              int tid) {
#pragma unroll
    for (int i = 0; i < (TILE_C * 4) / THREADS; i++) {   // 2 per thread
        int idx = tid + i * THREADS;
        int r = idx >> 2, c = idx & 3;
        unsigned int d = dst_s + r * (SROW * 2) + c * 16;
        const void* g = src + r * DIM + c * 8;
        asm volatile("cp.async.cg.shared.global [%0], [%1], 16;"
                     :: "r"(d), "l"(g) : "memory");
    }
    asm volatile("cp.async.commit_group;" ::: "memory");
}
__device__ __forceinline__ void cp_wait0() {
    asm volatile("cp.async.wait_group 0;" ::: "memory");
}

// ---- load the two k-half A fragments for one m16 tile (proven layout) ----
__device__ __forceinline__ void load_A(const unsigned short* sZ, int row,
                                       int qc, unsigned int* A0,
                                       unsigned int* A1) {
    A0[0] = *reinterpret_cast<const unsigned int*>(&sZ[row * SROW + qc]);
    A0[1] = *reinterpret_cast<const unsigned int*>(&sZ[(row + 8) * SROW + qc]);
    A0[2] = *reinterpret_cast<const unsigned int*>(&sZ[row * SROW + qc + 8]);
    A0[3] = *reinterpret_cast<const unsigned int*>(&sZ[(row + 8) * SROW + qc + 8]);
    A1[0] = *reinterpret_cast<const unsigned int*>(&sZ[row * SROW + qc + 16]);
    A1[1] = *reinterpret_cast<const unsigned int*>(&sZ[(row + 8) * SROW + qc + 16]);
    A1[2] = *reinterpret_cast<const unsigned int*>(&sZ[row * SROW + qc + 24]);
    A1[3] = *reinterpret_cast<const unsigned int*>(&sZ[(row + 8) * SROW + qc + 24]);
}

// ============================================================
// Kernel 3: PASS 1 — bf16 MMA sweep, per-point max approx dot
// cp.async double-buffered tiles; ITEMS=1024 for occupancy
// (launch #4 -> profiled)
// ============================================================
__global__ void __launch_bounds__(THREADS)
pass1_kernel() {
    __shared__ __align__(16) unsigned short sZ[PTS_PER_BLOCK * SROW];   // 20 KB
    __shared__ __align__(16) unsigned short sC[2][TILE_C * SROW];       // 2x10 KB

    const int tid  = threadIdx.x;
    const int w    = tid >> 5;
    const int lane = tid & 31;
    const int qr   = lane >> 2;          // 0..7
    const int qc   = (lane & 3) * 2;     // 0,2,4,6

    const unsigned int lds_off = ((lane & 7) * SROW + (lane >> 3) * 8) * 2;
    const unsigned int scbase0 = smem_u32(sC[0]);
    const unsigned int scbase1 = smem_u32(sC[1]);

    const int it = blockIdx.x;              // one item per block
    const int pg = it >> 3;                 // point group 0..127
    const int cr = it & 7;                  // code range 0..7
    const int p0 = pg * PTS_PER_BLOCK;
    const int c0r = cr * CODES_PER_RANGE;

    fill_z(sZ, g_znh + p0 * DIM, tid);
    prefetch_tile(scbase0, g_ewh + c0r * DIM, tid);
    __syncthreads();

    // two A tiles per warp: rows w*32 .. w*32+31
    const int ar0 = w * 32 + qr;
    const int ar1 = ar0 + 16;
    unsigned int A0[4], A1[4], A2[4], A3[4];
    load_A(sZ, ar0, qc, A0, A1);
    load_A(sZ, ar1, qc, A2, A3);

    float m0 = -2.0f, m1 = -2.0f, m2 = -2.0f, m3 = -2.0f;

    for (int t = 0; t < NTILES; t++) {
        cp_wait0();
        __syncthreads();
        if (t + 1 < NTILES)
            prefetch_tile((t & 1) ? scbase0 : scbase1,
                          g_ewh + (c0r + (t + 1) * TILE_C) * DIM, tid);
        const unsigned int sc0 = ((t & 1) ? scbase1 : scbase0) + lds_off;

#pragma unroll 4
        for (int nt = 0; nt < TILE_C / 8; nt++) {
            unsigned int B[4];
            ldsm_x4(B, sc0 + nt * (8 * SROW * 2));   // all 4 B frags
            float c0[4] = {0.f, 0.f, 0.f, 0.f};
            float c1[4] = {0.f, 0.f, 0.f, 0.f};
            hmma(c0, A0, B);
            hmma(c0, A1, B + 2);
            hmma(c1, A2, B);
            hmma(c1, A3, B + 2);
            m0 = fmaxf(m0, fmaxf(c0[0], c0[1]));
            m1 = fmaxf(m1, fmaxf(c0[2], c0[3]));
            m2 = fmaxf(m2, fmaxf(c1[0], c1[1]));
            m3 = fmaxf(m3, fmaxf(c1[2], c1[3]));
        }
    }
    // reduce max over the 4 threads of each quad (cols)
#pragma unroll
    for (int x = 1; x < 4; x <<= 1) {
        m0 = fmaxf(m0, __shfl_xor_sync(0xFFFFFFFFu, m0, x));
        m1 = fmaxf(m1, __shfl_xor_sync(0xFFFFFFFFu, m1, x));
        m2 = fmaxf(m2, __shfl_xor_sync(0xFFFFFFFFu, m2, x));
        m3 = fmaxf(m3, __shfl_xor_sync(0xFFFFFFFFu, m3, x));
    }
    if ((lane & 3) == 0) {
        atomicMax(&g_maxu[p0 + ar0],      fkey(m0));
        atomicMax(&g_maxu[p0 + ar0 + 8],  fkey(m1));
        atomicMax(&g_maxu[p0 + ar1],      fkey(m2));
        atomicMax(&g_maxu[p0 + ar1 + 8],  fkey(m3));
    }
}

// ============================================================
// Kernel 4: PASS 2 — same sweep (identical approx values), emit
// candidates >= max - MARGIN (final global max -> few cands/pt)
// ============================================================
__global__ void __launch_bounds__(THREADS)
pass2_kernel() {
    __shared__ __align__(16) unsigned short sZ[PTS_PER_BLOCK * SROW];
    __shared__ __align__(16) unsigned short sC[2][TILE_C * SROW];

    const int tid  = threadIdx.x;
    const int w    = tid >> 5;
    const int lane = tid & 31;
    const int qr   = lane >> 2;
    const int qc   = (lane & 3) * 2;

    const unsigned int lds_off = ((lane & 7) * SROW + (lane >> 3) * 8) * 2;
    const unsigned int scbase0 = smem_u32(sC[0]);
    const unsigned int scbase1 = smem_u32(sC[1]);

    const int it = blockIdx.x;
    const int pg = it >> 3;
    const int cr = it & 7;
    const int p0 = pg * PTS_PER_BLOCK;
    const int c0r = cr * CODES_PER_RANGE;

    fill_z(sZ, g_znh + p0 * DIM, tid);
    prefetch_tile(scbase0, g_ewh + c0r * DIM, tid);
    __syncthreads();

    const int ar0 = w * 32 + qr;
    const int ar1 = ar0 + 16;
    const int pt0 = p0 + ar0;
    const int pt1 = p0 + ar1;
    unsigned int A0[4], A1[4], A2[4], A3[4];
    load_A(sZ, ar0, qc, A0, A1);
    load_A(sZ, ar1, qc, A2, A3);

    const float th0 = finv(g_maxu[pt0])     - MARGIN;
    const float th1 = finv(g_maxu[pt0 + 8]) - MARGIN;
    const float th2 = finv(g_maxu[pt1])     - MARGIN;
    const float th3 = finv(g_maxu[pt1 + 8]) - MARGIN;

    for (int t = 0; t < NTILES; t++) {
        cp_wait0();
        __syncthreads();
        if (t + 1 < NTILES)
            prefetch_tile((t & 1) ? scbase0 : scbase1,
                          g_ewh + (c0r + (t + 1) * TILE_C) * DIM, tid);
        const unsigned int sc0 = ((t & 1) ? scbase1 : scbase0) + lds_off;

#pragma unroll 4
        for (int nt = 0; nt < TILE_C / 8; nt++) {
            unsigned int B[4];
            ldsm_x4(B, sc0 + nt * (8 * SROW * 2));
            float c0[4] = {0.f, 0.f, 0.f, 0.f};
            float c1[4] = {0.f, 0.f, 0.f, 0.f};
            hmma(c0, A0, B);
            hmma(c0, A1, B + 2);
            hmma(c1, A2, B);
            hmma(c1, A3, B + 2);

            if ((c0[0] >= th0) | (c0[1] >= th0) | (c0[2] >= th1) | (c0[3] >= th1) |
                (c1[0] >= th2) | (c1[1] >= th2) | (c1[2] >= th3) | (c1[3] >= th3)) {
                const int code0 = c0r + t * TILE_C + nt * 8 + qc;
                if (c0[0] >= th0) push_cand(pt0,     code0);
                if (c0[1] >= th0) push_cand(pt0,     code0 + 1);
                if (c0[2] >= th1) push_cand(pt0 + 8, code0);
                if (c0[3] >= th1) push_cand(pt0 + 8, code0 + 1);
                if (c1[0] >= th2) push_cand(pt1,     code0);
                if (c1[1] >= th2) push_cand(pt1,     code0 + 1);
                if (c1[2] >= th3) push_cand(pt1 + 8, code0);
                if (c1[3] >= th3) push_cand(pt1 + 8, code0 + 1);
            }
        }
    }
}

// ============================================================
// Kernel 5: exact fp32 rescore of candidates, atomicMax merge
// chain order (d mod 4, (S0+S2)+(S1+S3)) -> bit-identical dots
// ============================================================
__global__ void rescore_kernel() {
    const unsigned int n = g_ncand;
    const unsigned int lim = n < CAP ? n : CAP;
    for (unsigned int i = blockIdx.x * blockDim.x + threadIdx.x; i < lim;
         i += gridDim.x * blockDim.x) {
        const unsigned int e = g_cand[i];
        const int pt = e >> 13;
        const int k  = e & 8191;
        const float4* zp = reinterpret_cast<const float4*>(g_zn + pt * DIM);
        const float4* cp = reinterpret_cast<const float4*>(g_ew + k * DIM);
        float4 zv = zp[0], cv = cp[0];
        float s0 = zv.x * cv.x, s1 = zv.y * cv.y;
        float s2 = zv.z * cv.z, s3 = zv.w * cv.w;
#pragma unroll
        for (int h = 1; h < 8; h++) {
            zv = zp[h]; cv = cp[h];
            s0 = fmaf(zv.x, cv.x, s0);
            s1 = fmaf(zv.y, cv.y, s1);
            s2 = fmaf(zv.z, cv.z, s2);
            s3 = fmaf(zv.w, cv.w, s3);
        }
        const float dot = (s0 + s2) + (s1 + s3);
        unsigned long long pk =
            ((unsigned long long)fkey(dot) << 32) | (unsigned)(8191 - k);
        atomicMax(&g_bestpk[pt], pk);
    }
}

// ============================================================
// Kernel 6: finalize — idx + z_q (bchw) + histogram + loss partials
// ============================================================
__global__ void __launch_bounds__(THREADS)
finalize_kernel(float* __restrict__ out) {
    const int n = blockIdx.x * THREADS + threadIdx.x;

    const unsigned long long pk = g_bestpk[n];
    const int bi = 8191 - (int)(pk & 0xFFFFFFFFull);
    const float best = finv((unsigned int)(pk >> 32));

    out[N_PTS * DIM + 2 + n] = (float)bi;
    atomicAdd(&g_hist[bi], 1);

    const float4* ep = reinterpret_cast<const float4*>(g_ew + bi * DIM);
    const int b  = n >> 10;
    const int hw = n & 1023;
    float* op = out + b * (DIM * 1024) + hw;
#pragma unroll
    for (int i = 0; i < 8; i++) {
        float4 e = ep[i];
        op[(4 * i + 0) * 1024] = e.x;
        op[(4 * i + 1) * 1024] = e.y;
        op[(4 * i + 2) * 1024] = e.z;
        op[(4 * i + 3) * 1024] = e.w;
    }

    __shared__ float red[THREADS];
    red[threadIdx.x] = 2.0f - 2.0f * best;
    __syncthreads();
#pragma unroll
    for (int st = THREADS / 2; st > 0; st >>= 1) {
        if (threadIdx.x < st) red[threadIdx.x] += red[threadIdx.x + st];
        __syncthreads();
    }
    if (threadIdx.x == 0) g_part[blockIdx.x] = red[0];
}

// ============================================================
// Kernel 7: entropy partials
// ============================================================
__global__ void ent_kernel() {
    const int bin = blockIdx.x * 256 + threadIdx.x;
    const float denom = (float)N_PTS + (float)K_EMB * 1e-4f;
    const float invd  = 1.0f / denom;
    float p = ((float)g_hist[bin] + 1e-4f) * invd;
    __shared__ float sh[256];
    sh[threadIdx.x] = p * logf(p);
    __syncthreads();
#pragma unroll
    for (int st = 128; st > 0; st >>= 1) {
        if (threadIdx.x < st) sh[threadIdx.x] += sh[threadIdx.x + st];
        __syncthreads();
    }
    if (threadIdx.x == 0) g_entp[blockIdx.x] = sh[0];
}

// ============================================================
// Kernel 8: final scalars
// ============================================================
__global__ void scalars_kernel(float* __restrict__ out) {
    const int t = threadIdx.x;
    __shared__ float sh[THREADS];

    sh[t] = (t < 32) ? g_entp[t] : 0.f;
    __syncthreads();
#pragma unroll
    for (int st = THREADS / 2; st > 0; st >>= 1) {
        if (t < st) sh[t] += sh[t + st];
        __syncthreads();
    }
    float entropy = -sh[0];
    __syncthreads();

    sh[t] = (t < NBLK) ? g_part[t] : 0.f;
    __syncthreads();
#pragma unroll
    for (int st = THREADS / 2; st > 0; st >>= 1) {
        if (t < st) sh[t] += sh[t + st];
        __syncthreads();
    }
    if (t == 0) {
        out[N_PTS * DIM + 0] = 1.25f * (sh[0] / (float)N_PTS);
        out[N_PTS * DIM + 1] = entropy;
    }
}

// ============================================================
extern "C" void kernel_launch(void* const* d_in, const int* in_sizes, int n_in,
                              void* d_out, int out_size) {
    const float* z   = (const float*)d_in[0];
    const float* emb = (const float*)d_in[1];
    if (n_in >= 2 && in_sizes[0] == K_EMB * DIM && in_sizes[1] == N_PTS * DIM) {
        z   = (const float*)d_in[1];
        emb = (const float*)d_in[0];
    }
    float* out = (float*)d_out;

    init_kernel<<<N_PTS / THREADS, THREADS>>>();        // 1
    prep_emb<<<K_EMB / THREADS, THREADS>>>(emb);        // 2
    prep_z<<<N_PTS / THREADS, THREADS>>>(z);            // 3
    pass1_kernel<<<ITEMS, THREADS>>>();                 // 4 (profiled)
    pass2_kernel<<<ITEMS, THREADS>>>();                 // 5
    rescore_kernel<<<1024, THREADS>>>();                // 6
    finalize_kernel<<<NBLK, THREADS>>>(out);            // 7
    ent_kernel<<<32, 256>>>();                          // 8
    scalars_kernel<<<1, THREADS>>>(out);                // 9
}

// round 16
// speedup vs baseline: 1.1417x; 1.0027x over previous
#include <cuda_runtime.h>
#include <cuda_bf16.h>
#include <math.h>

#define N_PTS   32768
#define K_EMB   8192
#define DIM     32
#define THREADS 256
#define NBLK    (N_PTS / THREADS)        // 128
#define PTS_PER_BLOCK 256                // 8 warps * 32 pts (2 A-tiles each)
#define PTGRPS  (N_PTS / PTS_PER_BLOCK)  // 128
#define CRANGES 8
#define CODES_PER_RANGE (K_EMB / CRANGES)   // 1024
#define TILE_C  256                       // codes per smem tile (double-buffered)
#define NTILES  (CODES_PER_RANGE / TILE_C)  // 4
#define ITEMS   (PTGRPS * CRANGES)        // 1024
#define SROW    40                        // padded bf16 row stride
#define MARGIN  0.04f
#define CAP     (1u << 23)                // 8M candidate slots

#define SZ_USHORTS (PTS_PER_BLOCK * SROW)          // 10240
#define SC_USHORTS (TILE_C * SROW)                 // 10240
#define SMEM_BYTES ((SZ_USHORTS + 2 * SC_USHORTS) * 2)   // 61440

// ---- scratch (device globals; no allocation allowed) ----
__device__ float          g_ew [K_EMB * DIM];    // normalized codes fp32
__device__ unsigned short g_ewh[K_EMB * DIM];    // normalized codes bf16 bits
__device__ float          g_zn [N_PTS * DIM];    // normalized points fp32
__device__ unsigned short g_znh[N_PTS * DIM];    // normalized points bf16 bits
__device__ unsigned int   g_maxu[N_PTS];         // sortable max approx dot
__device__ unsigned long long g_bestpk[N_PTS];   // packed (key(dot)<<32)|(8191-idx)
__device__ unsigned int   g_ncand;
__device__ unsigned int   g_cand[CAP];           // (pt<<13)|code
__device__ int   g_hist[K_EMB];
__device__ float g_part[NBLK];
__device__ float g_entp[32];

// ---- sortable float <-> u32 ----
__device__ __forceinline__ unsigned int fkey(float f) {
    unsigned int s = __float_as_uint(f);
    return (s & 0x80000000u) ? ~s : (s | 0x80000000u);
}
__device__ __forceinline__ float finv(unsigned int k) {
    unsigned int s = (k & 0x80000000u) ? (k ^ 0x80000000u) : ~k;
    return __uint_as_float(s);
}

// ---- m16n8k16 bf16 MMA, fp32 accum ----
__device__ __forceinline__ void hmma(float* c, const unsigned int* a,
                                     const unsigned int* b) {
    asm volatile(
        "mma.sync.aligned.m16n8k16.row.col.f32.bf16.bf16.f32 "
        "{%0,%1,%2,%3}, {%4,%5,%6,%7}, {%8,%9}, {%0,%1,%2,%3};"
        : "+f"(c[0]), "+f"(c[1]), "+f"(c[2]), "+f"(c[3])
        : "r"(a[0]), "r"(a[1]), "r"(a[2]), "r"(a[3]),
          "r"(b[0]), "r"(b[1]));
}

// ---- ldmatrix x4: all four B fragments in one LDSM (layout proven R10) ----
__device__ __forceinline__ void ldsm_x4(unsigned int* r, unsigned int addr) {
    asm volatile(
        "ldmatrix.sync.aligned.m8n8.x4.shared.b16 {%0,%1,%2,%3}, [%4];"
        : "=r"(r[0]), "=r"(r[1]), "=r"(r[2]), "=r"(r[3]) : "r"(addr));
}

__device__ __forceinline__ unsigned int smem_u32(const void* p) {
    return (unsigned int)__cvta_generic_to_shared(p);
}

// ---- candidate push (only past-threshold; ~few per point) ----
__device__ __forceinline__ void push_cand(int pt, int code) {
    unsigned int p = atomicAdd(&g_ncand, 1u);
    if (p < CAP)
        g_cand[p] = ((unsigned)pt << 13) | (unsigned)code;
}

// ============================================================
// Kernel 1: FUSED prep — init scratch + normalize emb + normalize z
// blocks 0..127: z points (256 each) + per-point init
// blocks 128..159: emb rows (256 each) + hist zero
// ============================================================
__global__ void __launch_bounds__(THREADS)
prep_kernel(const float* __restrict__ z, const float* __restrict__ emb) {
    const int b = blockIdx.x;
    if (b < PTGRPS) {
        const int n = b * THREADS + threadIdx.x;   // 0..32767
        g_maxu[n] = 0u;
        g_bestpk[n] = 0ull;
        if (b == 0 && threadIdx.x == 0) g_ncand = 0u;

        const int bb = n >> 10;
        const int hw = n & 1023;
        const float* zp = z + bb * (DIM * 1024) + hw;
        float zn[DIM];
        float s = 0.f;
#pragma unroll
        for (int d = 0; d < DIM; d++) {
            float v = zp[d * 1024];
            zn[d] = v;
            s += v * v;
        }
        float inv = 1.0f / fmaxf(sqrtf(s), 1e-12f);
#pragma unroll
        for (int d = 0; d < DIM; d++) {
            float t = zn[d] * inv;
            g_zn [n * DIM + d] = t;
            g_znh[n * DIM + d] = __bfloat16_as_ushort(__float2bfloat16(t));
        }
    } else {
        const int r = (b - PTGRPS) * THREADS + threadIdx.x;  // 0..8191
        g_hist[r] = 0;

        const float4* src = reinterpret_cast<const float4*>(emb + r * DIM);
        float4 v[8];
        float s = 0.f;
#pragma unroll
        for (int i = 0; i < 8; i++) {
            v[i] = src[i];
            s += v[i].x * v[i].x + v[i].y * v[i].y + v[i].z * v[i].z + v[i].w * v[i].w;
        }
        float inv = 1.0f / fmaxf(sqrtf(s), 1e-12f);
        float4* dst = reinterpret_cast<float4*>(g_ew + r * DIM);
#pragma unroll
        for (int i = 0; i < 8; i++) {
            float4 o;
            o.x = v[i].x * inv; o.y = v[i].y * inv;
            o.z = v[i].z * inv; o.w = v[i].w * inv;
            dst[i] = o;
            g_ewh[r * DIM + 4 * i + 0] = __bfloat16_as_ushort(__float2bfloat16(o.x));
            g_ewh[r * DIM + 4 * i + 1] = __bfloat16_as_ushort(__float2bfloat16(o.y));
            g_ewh[r * DIM + 4 * i + 2] = __bfloat16_as_ushort(__float2bfloat16(o.z));
            g_ewh[r * DIM + 4 * i + 3] = __bfloat16_as_ushort(__float2bfloat16(o.w));
        }
    }
}

// ---- sZ fill: uint4 chunks (row = 64B payload = 4 chunks) ----
__device__ __forceinline__ void fill_z(unsigned short* dst,
                                       const unsigned short* src, int tid) {
    const uint4* s = reinterpret_cast<const uint4*>(src);
#pragma unroll
    for (int i = 0; i < (PTS_PER_BLOCK * 4) / THREADS; i++) {
        int idx = tid + i * THREADS;
        int r = idx >> 2, c = idx & 3;
        *reinterpret_cast<uint4*>(&dst[r * SROW + c * 8]) = s[idx];
    }
}

// ---- cp.async prefetch of one code tile (TILE_C rows, 16B chunks) ----
__device__ __forceinline__ void prefetch_tile(unsigned int dst_s,
                                              const unsigned short* src,
                                              int tid) {
#pragma unroll
    for (int i = 0; i < (TILE_C * 4) / THREADS; i++) {   // 4 per thread
        int idx = tid + i * THREADS;
        int r = idx >> 2, c = idx & 3;
        unsigned int d = dst_s + r * (SROW * 2) + c * 16;
        const void* g = src + r * DIM + c * 8;
        asm volatile("cp.async.cg.shared.global [%0], [%1], 16;"
                     :: "r"(d), "l"(g) : "memory");
    }
    asm volatile("cp.async.commit_group;" ::: "memory");
}
__device__ __forceinline__ void cp_wait0() {
    asm volatile("cp.async.wait_group 0;" ::: "memory");
}

// ---- load the two k-half A fragments for one m16 tile (proven layout) ----
__device__ __forceinline__ void load_A(const unsigned short* sZ, int row,
                                       int qc, unsigned int* A0,
                                       unsigned int* A1) {
    A0[0] = *reinterpret_cast<const unsigned int*>(&sZ[row * SROW + qc]);
    A0[1] = *reinterpret_cast<const unsigned int*>(&sZ[(row + 8) * SROW + qc]);
    A0[2] = *reinterpret_cast<const unsigned int*>(&sZ[row * SROW + qc + 8]);
    A0[3] = *reinterpret_cast<const unsigned int*>(&sZ[(row + 8) * SROW + qc + 8]);
    A1[0] = *reinterpret_cast<const unsigned int*>(&sZ[row * SROW + qc + 16]);
    A1[1] = *reinterpret_cast<const unsigned int*>(&sZ[(row + 8) * SROW + qc + 16]);
    A1[2] = *reinterpret_cast<const unsigned int*>(&sZ[row * SROW + qc + 24]);
    A1[3] = *reinterpret_cast<const unsigned int*>(&sZ[(row + 8) * SROW + qc + 24]);
}

// ============================================================
// Kernel 2: PASS 1 — bf16 MMA sweep, per-point max approx dot
// TILE_C=256 double-buffered (dynamic smem) -> half the barriers
// ============================================================
__global__ void __launch_bounds__(THREADS)
pass1_kernel() {
    extern __shared__ __align__(16) unsigned short smem[];
    unsigned short* sZ  = smem;                         // 20 KB
    unsigned short* sC0 = smem + SZ_USHORTS;            // 20 KB
    unsigned short* sC1 = sC0 + SC_USHORTS;             // 20 KB

    const int tid  = threadIdx.x;
    const int w    = tid >> 5;
    const int lane = tid & 31;
    const int qr   = lane >> 2;          // 0..7
    const int qc   = (lane & 3) * 2;     // 0,2,4,6

    const unsigned int lds_off = ((lane & 7) * SROW + (lane >> 3) * 8) * 2;
    const unsigned int scbase0 = smem_u32(sC0);
    const unsigned int scbase1 = smem_u32(sC1);

    const int it = blockIdx.x;              // one item per block
    const int pg = it >> 3;                 // point group 0..127
    const int cr = it & 7;                  // code range 0..7
    const int p0 = pg * PTS_PER_BLOCK;
    const int c0r = cr * CODES_PER_RANGE;

    fill_z(sZ, g_znh + p0 * DIM, tid);
    prefetch_tile(scbase0, g_ewh + c0r * DIM, tid);
    __syncthreads();

    // two A tiles per warp: rows w*32 .. w*32+31
    const int ar0 = w * 32 + qr;
    const int ar1 = ar0 + 16;
    unsigned int A0[4], A1[4], A2[4], A3[4];
    load_A(sZ, ar0, qc, A0, A1);
    load_A(sZ, ar1, qc, A2, A3);

    float m0 = -2.0f, m1 = -2.0f, m2 = -2.0f, m3 = -2.0f;

    for (int t = 0; t < NTILES; t++) {
        cp_wait0();
        __syncthreads();
        if (t + 1 < NTILES)
            prefetch_tile((t & 1) ? scbase0 : scbase1,
                          g_ewh + (c0r + (t + 1) * TILE_C) * DIM, tid);
        const unsigned int sc0 = ((t & 1) ? scbase1 : scbase0) + lds_off;

#pragma unroll 4
        for (int nt = 0; nt < TILE_C / 8; nt++) {
            unsigned int B[4];
            ldsm_x4(B, sc0 + nt * (8 * SROW * 2));   // all 4 B frags
            float c0[4] = {0.f, 0.f, 0.f, 0.f};
            float c1[4] = {0.f, 0.f, 0.f, 0.f};
            hmma(c0, A0, B);
            hmma(c0, A1, B + 2);
            hmma(c1, A2, B);
            hmma(c1, A3, B + 2);
            m0 = fmaxf(m0, fmaxf(c0[0], c0[1]));
            m1 = fmaxf(m1, fmaxf(c0[2], c0[3]));
            m2 = fmaxf(m2, fmaxf(c1[0], c1[1]));
            m3 = fmaxf(m3, fmaxf(c1[2], c1[3]));
        }
    }
    // reduce max over the 4 threads of each quad (cols)
#pragma unroll
    for (int x = 1; x < 4; x <<= 1) {
        m0 = fmaxf(m0, __shfl_xor_sync(0xFFFFFFFFu, m0, x));
        m1 = fmaxf(m1, __shfl_xor_sync(0xFFFFFFFFu, m1, x));
        m2 = fmaxf(m2, __shfl_xor_sync(0xFFFFFFFFu, m2, x));
        m3 = fmaxf(m3, __shfl_xor_sync(0xFFFFFFFFu, m3, x));
    }
    if ((lane & 3) == 0) {
        atomicMax(&g_maxu[p0 + ar0],      fkey(m0));
        atomicMax(&g_maxu[p0 + ar0 + 8],  fkey(m1));
        atomicMax(&g_maxu[p0 + ar1],      fkey(m2));
        atomicMax(&g_maxu[p0 + ar1 + 8],  fkey(m3));
    }
}

// ============================================================
// Kernel 3: PASS 2 — same sweep (identical approx values), emit
// candidates >= max - MARGIN   (launch #4 -> profiled this round)
// ============================================================
__global__ void __launch_bounds__(THREADS)
pass2_kernel() {
    extern __shared__ __align__(16) unsigned short smem[];
    unsigned short* sZ  = smem;
    unsigned short* sC0 = smem + SZ_USHORTS;
    unsigned short* sC1 = sC0 + SC_USHORTS;

    const int tid  = threadIdx.x;
    const int w    = tid >> 5;
    const int lane = tid & 31;
    const int qr   = lane >> 2;
    const int qc   = (lane & 3) * 2;

    const unsigned int lds_off = ((lane & 7) * SROW + (lane >> 3) * 8) * 2;
    const unsigned int scbase0 = smem_u32(sC0);
    const unsigned int scbase1 = smem_u32(sC1);

    const int it = blockIdx.x;
    const int pg = it >> 3;
    const int cr = it & 7;
    const int p0 = pg * PTS_PER_BLOCK;
    const int c0r = cr * CODES_PER_RANGE;

    fill_z(sZ, g_znh + p0 * DIM, tid);
    prefetch_tile(scbase0, g_ewh + c0r * DIM, tid);
    __syncthreads();

    const int ar0 = w * 32 + qr;
    const int ar1 = ar0 + 16;
    const int pt0 = p0 + ar0;
    const int pt1 = p0 + ar1;
    unsigned int A0[4], A1[4], A2[4], A3[4];
    load_A(sZ, ar0, qc, A0, A1);
    load_A(sZ, ar1, qc, A2, A3);

    const float th0 = finv(g_maxu[pt0])     - MARGIN;
    const float th1 = finv(g_maxu[pt0 + 8]) - MARGIN;
    const float th2 = finv(g_maxu[pt1])     - MARGIN;
    const float th3 = finv(g_maxu[pt1 + 8]) - MARGIN;

    for (int t = 0; t < NTILES; t++) {
        cp_wait0();
        __syncthreads();
        if (t + 1 < NTILES)
            prefetch_tile((t & 1) ? scbase0 : scbase1,
                          g_ewh + (c0r + (t + 1) * TILE_C) * DIM, tid);
        const unsigned int sc0 = ((t & 1) ? scbase1 : scbase0) + lds_off;

#pragma unroll 4
        for (int nt = 0; nt < TILE_C / 8; nt++) {
            unsigned int B[4];
            ldsm_x4(B, sc0 + nt * (8 * SROW * 2));
            float c0[4] = {0.f, 0.f, 0.f, 0.f};
            float c1[4] = {0.f, 0.f, 0.f, 0.f};
            hmma(c0, A0, B);
            hmma(c0, A1, B + 2);
            hmma(c1, A2, B);
            hmma(c1, A3, B + 2);

            if ((c0[0] >= th0) | (c0[1] >= th0) | (c0[2] >= th1) | (c0[3] >= th1) |
                (c1[0] >= th2) | (c1[1] >= th2) | (c1[2] >= th3) | (c1[3] >= th3)) {
                const int code0 = c0r + t * TILE_C + nt * 8 + qc;
                if (c0[0] >= th0) push_cand(pt0,     code0);
                if (c0[1] >= th0) push_cand(pt0,     code0 + 1);
                if (c0[2] >= th1) push_cand(pt0 + 8, code0);
                if (c0[3] >= th1) push_cand(pt0 + 8, code0 + 1);
                if (c1[0] >= th2) push_cand(pt1,     code0);
                if (c1[1] >= th2) push_cand(pt1,     code0 + 1);
                if (c1[2] >= th3) push_cand(pt1 + 8, code0);
                if (c1[3] >= th3) push_cand(pt1 + 8, code0 + 1);
            }
        }
    }
}

// ============================================================
// Kernel 4: exact fp32 rescore of candidates, atomicMax merge
// chain order (d mod 4, (S0+S2)+(S1+S3)) -> bit-identical dots
// ============================================================
__global__ void rescore_kernel() {
    const unsigned int n = g_ncand;
    const unsigned int lim = n < CAP ? n : CAP;
    for (unsigned int i = blockIdx.x * blockDim.x + threadIdx.x; i < lim;
         i += gridDim.x * blockDim.x) {
        const unsigned int e = g_cand[i];
        const int pt = e >> 13;
        const int k  = e & 8191;
        const float4* zp = reinterpret_cast<const float4*>(g_zn + pt * DIM);
        const float4* cp = reinterpret_cast<const float4*>(g_ew + k * DIM);
        float4 zv = zp[0], cv = cp[0];
        float s0 = zv.x * cv.x, s1 = zv.y * cv.y;
        float s2 = zv.z * cv.z, s3 = zv.w * cv.w;
#pragma unroll
        for (int h = 1; h < 8; h++) {
            zv = zp[h]; cv = cp[h];
            s0 = fmaf(zv.x, cv.x, s0);
            s1 = fmaf(zv.y, cv.y, s1);
            s2 = fmaf(zv.z, cv.z, s2);
            s3 = fmaf(zv.w, cv.w, s3);
        }
        const float dot = (s0 + s2) + (s1 + s3);
        unsigned long long pk =
            ((unsigned long long)fkey(dot) << 32) | (unsigned)(8191 - k);
        atomicMax(&g_bestpk[pt], pk);
    }
}

// ============================================================
// Kernel 5: finalize — idx + z_q (bchw) + histogram + loss partials
// ============================================================
__global__ void __launch_bounds__(THREADS)
finalize_kernel(float* __restrict__ out) {
    const int n = blockIdx.x * THREADS + threadIdx.x;

    const unsigned long long pk = g_bestpk[n];
    const int bi = 8191 - (int)(pk & 0xFFFFFFFFull);
    const float best = finv((unsigned int)(pk >> 32));

    out[N_PTS * DIM + 2 + n] = (float)bi;
    atomicAdd(&g_hist[bi], 1);

    const float4* ep = reinterpret_cast<const float4*>(g_ew + bi * DIM);
    const int b  = n >> 10;
    const int hw = n & 1023;
    float* op = out + b * (DIM * 1024) + hw;
#pragma unroll
    for (int i = 0; i < 8; i++) {
        float4 e = ep[i];
        op[(4 * i + 0) * 1024] = e.x;
        op[(4 * i + 1) * 1024] = e.y;
        op[(4 * i + 2) * 1024] = e.z;
        op[(4 * i + 3) * 1024] = e.w;
    }

    __shared__ float red[THREADS];
    red[threadIdx.x] = 2.0f - 2.0f * best;
    __syncthreads();
#pragma unroll
    for (int st = THREADS / 2; st > 0; st >>= 1) {
        if (threadIdx.x < st) red[threadIdx.x] += red[threadIdx.x + st];
        __syncthreads();
    }
    if (threadIdx.x == 0) g_part[blockIdx.x] = red[0];
}

// ============================================================
// Kernel 6: entropy partials
// ============================================================
__global__ void ent_kernel() {
    const int bin = blockIdx.x * 256 + threadIdx.x;
    const float denom = (float)N_PTS + (float)K_EMB * 1e-4f;
    const float invd  = 1.0f / denom;
    float p = ((float)g_hist[bin] + 1e-4f) * invd;
    __shared__ float sh[256];
    sh[threadIdx.x] = p * logf(p);
    __syncthreads();
#pragma unroll
    for (int st = 128; st > 0; st >>= 1) {
        if (threadIdx.x < st) sh[threadIdx.x] += sh[threadIdx.x + st];
        __syncthreads();
    }
    if (threadIdx.x == 0) g_entp[blockIdx.x] = sh[0];
}

// ============================================================
// Kernel 7: final scalars
// ============================================================
__global__ void scalars_kernel(float* __restrict__ out) {
    const int t = threadIdx.x;
    __shared__ float sh[THREADS];

    sh[t] = (t < 32) ? g_entp[t] : 0.f;
    __syncthreads();
#pragma unroll
    for (int st = THREADS / 2; st > 0; st >>= 1) {
        if (t < st) sh[t] += sh[t + st];
        __syncthreads();
    }
    float entropy = -sh[0];
    __syncthreads();

    sh[t] = (t < NBLK) ? g_part[t] : 0.f;
    __syncthreads();
#pragma unroll
    for (int st = THREADS / 2; st > 0; st >>= 1) {
        if (t < st) sh[t] += sh[t + st];
        __syncthreads();
    }
    if (t == 0) {
        out[N_PTS * DIM + 0] = 1.25f * (sh[0] / (float)N_PTS);
        out[N_PTS * DIM + 1] = entropy;
    }
}

// ============================================================
extern "C" void kernel_launch(void* const* d_in, const int* in_sizes, int n_in,
                              void* d_out, int out_size) {
    const float* z   = (const float*)d_in[0];
    const float* emb = (const float*)d_in[1];
    if (n_in >= 2 && in_sizes[0] == K_EMB * DIM && in_sizes[1] == N_PTS * DIM) {
        z   = (const float*)d_in[1];
        emb = (const float*)d_in[0];
    }
    float* out = (float*)d_out;

    // raise dynamic smem limit (host-side, idempotent, capture-safe)
    cudaFuncSetAttribute(pass1_kernel,
                         cudaFuncAttributeMaxDynamicSharedMemorySize, SMEM_BYTES);
    cudaFuncSetAttribute(pass2_kernel,
                         cudaFuncAttributeMaxDynamicSharedMemorySize, SMEM_BYTES);

    prep_kernel<<<PTGRPS + K_EMB / THREADS, THREADS>>>(z, emb);   // 1
    pass1_kernel<<<ITEMS, THREADS, SMEM_BYTES>>>();               // 2
    pass2_kernel<<<ITEMS, THREADS, SMEM_BYTES>>>();               // 3 ... wait
    rescore_kernel<<<1024, THREADS>>>();                          // 4 (profiled)
    finalize_kernel<<<NBLK, THREADS>>>(out);                      // 5
    ent_kernel<<<32, 256>>>();                                    // 6
    scalars_kernel<<<1, THREADS>>>(out);                          // 7
}

// round 17
// speedup vs baseline: 1.1483x; 1.0057x over previous
#include <cuda_runtime.h>
#include <cuda_bf16.h>
#include <math.h>

#define N_PTS   32768
#define K_EMB   8192
#define DIM     32
#define THREADS 256
#define NBLK    (N_PTS / THREADS)        // 128
#define PTS_PER_BLOCK 256                // 8 warps * 32 pts (2 A-tiles each)
#define PTGRPS  (N_PTS / PTS_PER_BLOCK)  // 128
#define CRANGES 8
#define CODES_PER_RANGE (K_EMB / CRANGES)   // 1024
#define TILE_C  256                       // codes per smem tile (double-buffered)
#define NTILES  (CODES_PER_RANGE / TILE_C)  // 4
#define ITEMS   (PTGRPS * CRANGES)        // 1024
#define SROW    40                        // padded bf16 row stride
#define MARGIN  0.04f
#define CAP     (1u << 23)                // 8M candidate slots

#define SZ_USHORTS (PTS_PER_BLOCK * SROW)          // 10240
#define SC_USHORTS (TILE_C * SROW)                 // 10240
#define SMEM_BYTES ((SZ_USHORTS + 2 * SC_USHORTS) * 2)   // 61440

// ---- scratch (device globals; no allocation allowed) ----
__device__ float          g_ew [K_EMB * DIM];    // normalized codes fp32
__device__ unsigned short g_ewh[K_EMB * DIM];    // normalized codes bf16 bits
__device__ float          g_zn [N_PTS * DIM];    // normalized points fp32
__device__ unsigned short g_znh[N_PTS * DIM];    // normalized points bf16 bits
__device__ unsigned int   g_maxu[N_PTS];         // sortable max approx dot
__device__ unsigned long long g_bestpk[N_PTS];   // packed (key(dot)<<32)|(8191-idx)
__device__ unsigned int   g_ncand;
__device__ unsigned int   g_cand[CAP];           // (pt<<13)|code
__device__ int   g_hist[K_EMB];
__device__ float g_part[NBLK];
__device__ float g_entp[32];

// ---- sortable float <-> u32 ----
__device__ __forceinline__ unsigned int fkey(float f) {
    unsigned int s = __float_as_uint(f);
    return (s & 0x80000000u) ? ~s : (s | 0x80000000u);
}
__device__ __forceinline__ float finv(unsigned int k) {
    unsigned int s = (k & 0x80000000u) ? (k ^ 0x80000000u) : ~k;
    return __uint_as_float(s);
}

// ---- m16n8k16 bf16 MMA, fp32 accum ----
__device__ __forceinline__ void hmma(float* c, const unsigned int* a,
                                     const unsigned int* b) {
    asm volatile(
        "mma.sync.aligned.m16n8k16.row.col.f32.bf16.bf16.f32 "
        "{%0,%1,%2,%3}, {%4,%5,%6,%7}, {%8,%9}, {%0,%1,%2,%3};"
        : "+f"(c[0]), "+f"(c[1]), "+f"(c[2]), "+f"(c[3])
        : "r"(a[0]), "r"(a[1]), "r"(a[2]), "r"(a[3]),
          "r"(b[0]), "r"(b[1]));
}

// ---- ldmatrix x4: all four B fragments in one LDSM (layout proven R10) ----
__device__ __forceinline__ void ldsm_x4(unsigned int* r, unsigned int addr) {
    asm volatile(
        "ldmatrix.sync.aligned.m8n8.x4.shared.b16 {%0,%1,%2,%3}, [%4];"
        : "=r"(r[0]), "=r"(r[1]), "=r"(r[2]), "=r"(r[3]) : "r"(addr));
}

__device__ __forceinline__ unsigned int smem_u32(const void* p) {
    return (unsigned int)__cvta_generic_to_shared(p);
}

// ---- candidate push (only past-threshold; ~few per point) ----
__device__ __forceinline__ void push_cand(int pt, int code) {
    unsigned int p = atomicAdd(&g_ncand, 1u);
    if (p < CAP)
        g_cand[p] = ((unsigned)pt << 13) | (unsigned)code;
}

// ============================================================
// Kernel 1: prep_z — per-point init + normalize z (bchw gather)
// ============================================================
__global__ void __launch_bounds__(THREADS)
prep_z_kernel(const float* __restrict__ z) {
    const int n = blockIdx.x * THREADS + threadIdx.x;   // 0..32767
    g_maxu[n] = 0u;
    g_bestpk[n] = 0ull;
    if (n == 0) g_ncand = 0u;

    const int bb = n >> 10;
    const int hw = n & 1023;
    const float* zp = z + bb * (DIM * 1024) + hw;
    float zn[DIM];
    float s = 0.f;
#pragma unroll
    for (int d = 0; d < DIM; d++) {
        float v = zp[d * 1024];
        zn[d] = v;
        s += v * v;
    }
    float inv = 1.0f / fmaxf(sqrtf(s), 1e-12f);
#pragma unroll
    for (int d = 0; d < DIM; d++) {
        float t = zn[d] * inv;
        g_zn [n * DIM + d] = t;
        g_znh[n * DIM + d] = __bfloat16_as_ushort(__float2bfloat16(t));
    }
}

// ============================================================
// Kernel 2: prep_emb — hist zero + normalize embedding
// ============================================================
__global__ void __launch_bounds__(THREADS)
prep_emb_kernel(const float* __restrict__ emb) {
    const int r = blockIdx.x * THREADS + threadIdx.x;  // 0..8191
    g_hist[r] = 0;

    const float4* src = reinterpret_cast<const float4*>(emb + r * DIM);
    float4 v[8];
    float s = 0.f;
#pragma unroll
    for (int i = 0; i < 8; i++) {
        v[i] = src[i];
        s += v[i].x * v[i].x + v[i].y * v[i].y + v[i].z * v[i].z + v[i].w * v[i].w;
    }
    float inv = 1.0f / fmaxf(sqrtf(s), 1e-12f);
    float4* dst = reinterpret_cast<float4*>(g_ew + r * DIM);
#pragma unroll
    for (int i = 0; i < 8; i++) {
        float4 o;
        o.x = v[i].x * inv; o.y = v[i].y * inv;
        o.z = v[i].z * inv; o.w = v[i].w * inv;
        dst[i] = o;
        g_ewh[r * DIM + 4 * i + 0] = __bfloat16_as_ushort(__float2bfloat16(o.x));
        g_ewh[r * DIM + 4 * i + 1] = __bfloat16_as_ushort(__float2bfloat16(o.y));
        g_ewh[r * DIM + 4 * i + 2] = __bfloat16_as_ushort(__float2bfloat16(o.z));
        g_ewh[r * DIM + 4 * i + 3] = __bfloat16_as_ushort(__float2bfloat16(o.w));
    }
}

// ---- sZ fill: uint4 chunks (row = 64B payload = 4 chunks) ----
__device__ __forceinline__ void fill_z(unsigned short* dst,
                                       const unsigned short* src, int tid) {
    const uint4* s = reinterpret_cast<const uint4*>(src);
#pragma unroll
    for (int i = 0; i < (PTS_PER_BLOCK * 4) / THREADS; i++) {
        int idx = tid + i * THREADS;
        int r = idx >> 2, c = idx & 3;
        *reinterpret_cast<uint4*>(&dst[r * SROW + c * 8]) = s[idx];
    }
}

// ---- cp.async prefetch of one code tile (TILE_C rows, 16B chunks) ----
__device__ __forceinline__ void prefetch_tile(unsigned int dst_s,
                                              const unsigned short* src,
                                              int tid) {
#pragma unroll
    for (int i = 0; i < (TILE_C * 4) / THREADS; i++) {   // 4 per thread
        int idx = tid + i * THREADS;
        int r = idx >> 2, c = idx & 3;
        unsigned int d = dst_s + r * (SROW * 2) + c * 16;
        const void* g = src + r * DIM + c * 8;
        asm volatile("cp.async.cg.shared.global [%0], [%1], 16;"
                     :: "r"(d), "l"(g) : "memory");
    }
    asm volatile("cp.async.commit_group;" ::: "memory");
}
__device__ __forceinline__ void cp_wait0() {
    asm volatile("cp.async.wait_group 0;" ::: "memory");
}

// ---- load the two k-half A fragments for one m16 tile (proven layout) ----
__device__ __forceinline__ void load_A(const unsigned short* sZ, int row,
                                       int qc, unsigned int* A0,
                                       unsigned int* A1) {
    A0[0] = *reinterpret_cast<const unsigned int*>(&sZ[row * SROW + qc]);
    A0[1] = *reinterpret_cast<const unsigned int*>(&sZ[(row + 8) * SROW + qc]);
    A0[2] = *reinterpret_cast<const unsigned int*>(&sZ[row * SROW + qc + 8]);
    A0[3] = *reinterpret_cast<const unsigned int*>(&sZ[(row + 8) * SROW + qc + 8]);
    A1[0] = *reinterpret_cast<const unsigned int*>(&sZ[row * SROW + qc + 16]);
    A1[1] = *reinterpret_cast<const unsigned int*>(&sZ[(row + 8) * SROW + qc + 16]);
    A1[2] = *reinterpret_cast<const unsigned int*>(&sZ[row * SROW + qc + 24]);
    A1[3] = *reinterpret_cast<const unsigned int*>(&sZ[(row + 8) * SROW + qc + 24]);
}

// ============================================================
// Kernel 3: PASS 1 — bf16 MMA sweep, per-point max approx dot
// interleaved c0/c1 HMMAs for 2-deep tensor ILP
// ============================================================
__global__ void __launch_bounds__(THREADS)
pass1_kernel() {
    extern __shared__ __align__(16) unsigned short smem[];
    unsigned short* sZ  = smem;                         // 20 KB
    unsigned short* sC0 = smem + SZ_USHORTS;            // 20 KB
    unsigned short* sC1 = sC0 + SC_USHORTS;             // 20 KB

    const int tid  = threadIdx.x;
    const int w    = tid >> 5;
    const int lane = tid & 31;
    const int qr   = lane >> 2;          // 0..7
    const int qc   = (lane & 3) * 2;     // 0,2,4,6

    const unsigned int lds_off = ((lane & 7) * SROW + (lane >> 3) * 8) * 2;
    const unsigned int scbase0 = smem_u32(sC0);
    const unsigned int scbase1 = smem_u32(sC1);

    const int it = blockIdx.x;              // one item per block
    const int pg = it >> 3;                 // point group 0..127
    const int cr = it & 7;                  // code range 0..7
    const int p0 = pg * PTS_PER_BLOCK;
    const int c0r = cr * CODES_PER_RANGE;

    fill_z(sZ, g_znh + p0 * DIM, tid);
    prefetch_tile(scbase0, g_ewh + c0r * DIM, tid);
    __syncthreads();

    // two A tiles per warp: rows w*32 .. w*32+31
    const int ar0 = w * 32 + qr;
    const int ar1 = ar0 + 16;
    unsigned int A0[4], A1[4], A2[4], A3[4];
    load_A(sZ, ar0, qc, A0, A1);
    load_A(sZ, ar1, qc, A2, A3);

    float m0 = -2.0f, m1 = -2.0f, m2 = -2.0f, m3 = -2.0f;

    for (int t = 0; t < NTILES; t++) {
        cp_wait0();
        __syncthreads();
        if (t + 1 < NTILES)
            prefetch_tile((t & 1) ? scbase0 : scbase1,
                          g_ewh + (c0r + (t + 1) * TILE_C) * DIM, tid);
        const unsigned int sc0 = ((t & 1) ? scbase1 : scbase0) + lds_off;

#pragma unroll 4
        for (int nt = 0; nt < TILE_C / 8; nt++) {
            unsigned int B[4];
            ldsm_x4(B, sc0 + nt * (8 * SROW * 2));   // all 4 B frags
            float c0[4] = {0.f, 0.f, 0.f, 0.f};
            float c1[4] = {0.f, 0.f, 0.f, 0.f};
            hmma(c0, A0, B);        // interleave c0/c1 chains: 2-deep ILP,
            hmma(c1, A2, B);        // per-accumulator order unchanged
            hmma(c0, A1, B + 2);
            hmma(c1, A3, B + 2);
            m0 = fmaxf(m0, fmaxf(c0[0], c0[1]));
            m1 = fmaxf(m1, fmaxf(c0[2], c0[3]));
            m2 = fmaxf(m2, fmaxf(c1[0], c1[1]));
            m3 = fmaxf(m3, fmaxf(c1[2], c1[3]));
        }
    }
    // reduce max over the 4 threads of each quad (cols)
#pragma unroll
    for (int x = 1; x < 4; x <<= 1) {
        m0 = fmaxf(m0, __shfl_xor_sync(0xFFFFFFFFu, m0, x));
        m1 = fmaxf(m1, __shfl_xor_sync(0xFFFFFFFFu, m1, x));
        m2 = fmaxf(m2, __shfl_xor_sync(0xFFFFFFFFu, m2, x));
        m3 = fmaxf(m3, __shfl_xor_sync(0xFFFFFFFFu, m3, x));
    }
    if ((lane & 3) == 0) {
        atomicMax(&g_maxu[p0 + ar0],      fkey(m0));
        atomicMax(&g_maxu[p0 + ar0 + 8],  fkey(m1));
        atomicMax(&g_maxu[p0 + ar1],      fkey(m2));
        atomicMax(&g_maxu[p0 + ar1 + 8],  fkey(m3));
    }
}

// ============================================================
// Kernel 4: PASS 2 — same sweep (identical approx values), emit
// candidates >= max - MARGIN   (launch #4 -> profiled this round)
// ============================================================
__global__ void __launch_bounds__(THREADS)
pass2_kernel() {
    extern __shared__ __align__(16) unsigned short smem[];
    unsigned short* sZ  = smem;
    unsigned short* sC0 = smem + SZ_USHORTS;
    unsigned short* sC1 = sC0 + SC_USHORTS;

    const int tid  = threadIdx.x;
    const int w    = tid >> 5;
    const int lane = tid & 31;
    const int qr   = lane >> 2;
    const int qc   = (lane & 3) * 2;

    const unsigned int lds_off = ((lane & 7) * SROW + (lane >> 3) * 8) * 2;
    const unsigned int scbase0 = smem_u32(sC0);
    const unsigned int scbase1 = smem_u32(sC1);

    const int it = blockIdx.x;
    const int pg = it >> 3;
    const int cr = it & 7;
    const int p0 = pg * PTS_PER_BLOCK;
    const int c0r = cr * CODES_PER_RANGE;

    fill_z(sZ, g_znh + p0 * DIM, tid);
    prefetch_tile(scbase0, g_ewh + c0r * DIM, tid);
    __syncthreads();

    const int ar0 = w * 32 + qr;
    const int ar1 = ar0 + 16;
    const int pt0 = p0 + ar0;
    const int pt1 = p0 + ar1;
    unsigned int A0[4], A1[4], A2[4], A3[4];
    load_A(sZ, ar0, qc, A0, A1);
    load_A(sZ, ar1, qc, A2, A3);

    const float th0 = finv(g_maxu[pt0])     - MARGIN;
    const float th1 = finv(g_maxu[pt0 + 8]) - MARGIN;
    const float th2 = finv(g_maxu[pt1])     - MARGIN;
    const float th3 = finv(g_maxu[pt1 + 8]) - MARGIN;

    for (int t = 0; t < NTILES; t++) {
        cp_wait0();
        __syncthreads();
        if (t + 1 < NTILES)
            prefetch_tile((t & 1) ? scbase0 : scbase1,
                          g_ewh + (c0r + (t + 1) * TILE_C) * DIM, tid);
        const unsigned int sc0 = ((t & 1) ? scbase1 : scbase0) + lds_off;

#pragma unroll 4
        for (int nt = 0; nt < TILE_C / 8; nt++) {
            unsigned int B[4];
            ldsm_x4(B, sc0 + nt * (8 * SROW * 2));
            float c0[4] = {0.f, 0.f, 0.f, 0.f};
            float c1[4] = {0.f, 0.f, 0.f, 0.f};
            hmma(c0, A0, B);
            hmma(c1, A2, B);
            hmma(c0, A1, B + 2);
            hmma(c1, A3, B + 2);

            if ((c0[0] >= th0) | (c0[1] >= th0) | (c0[2] >= th1) | (c0[3] >= th1) |
                (c1[0] >= th2) | (c1[1] >= th2) | (c1[2] >= th3) | (c1[3] >= th3)) {
                const int code0 = c0r + t * TILE_C + nt * 8 + qc;
                if (c0[0] >= th0) push_cand(pt0,     code0);
                if (c0[1] >= th0) push_cand(pt0,     code0 + 1);
                if (c0[2] >= th1) push_cand(pt0 + 8, code0);
                if (c0[3] >= th1) push_cand(pt0 + 8, code0 + 1);
                if (c1[0] >= th2) push_cand(pt1,     code0);
                if (c1[1] >= th2) push_cand(pt1,     code0 + 1);
                if (c1[2] >= th3) push_cand(pt1 + 8, code0);
                if (c1[3] >= th3) push_cand(pt1 + 8, code0 + 1);
            }
        }
    }
}

// ============================================================
// Kernel 5: exact fp32 rescore of candidates, atomicMax merge
// grid 256 (was 1024): same work, 1/4 the idle-thread overhead
// ============================================================
__global__ void __launch_bounds__(THREADS)
rescore_kernel() {
    __shared__ unsigned int s_n;
    if (threadIdx.x == 0) s_n = g_ncand;
    __syncthreads();
    const unsigned int lim = s_n < CAP ? s_n : CAP;
    for (unsigned int i = blockIdx.x * blockDim.x + threadIdx.x; i < lim;
         i += gridDim.x * blockDim.x) {
        const unsigned int e = g_cand[i];
        const int pt = e >> 13;
        const int k  = e & 8191;
        const float4* zp = reinterpret_cast<const float4*>(g_zn + pt * DIM);
        const float4* cp = reinterpret_cast<const float4*>(g_ew + k * DIM);
        float4 zv = zp[0], cv = cp[0];
        float s0 = zv.x * cv.x, s1 = zv.y * cv.y;
        float s2 = zv.z * cv.z, s3 = zv.w * cv.w;
#pragma unroll
        for (int h = 1; h < 8; h++) {
            zv = zp[h]; cv = cp[h];
            s0 = fmaf(zv.x, cv.x, s0);
            s1 = fmaf(zv.y, cv.y, s1);
            s2 = fmaf(zv.z, cv.z, s2);
            s3 = fmaf(zv.w, cv.w, s3);
        }
        const float dot = (s0 + s2) + (s1 + s3);
        unsigned long long pk =
            ((unsigned long long)fkey(dot) << 32) | (unsigned)(8191 - k);
        atomicMax(&g_bestpk[pt], pk);
    }
}

// ============================================================
// Kernel 6: finalize — idx + z_q (bchw) + histogram + loss partials
// ============================================================
__global__ void __launch_bounds__(THREADS)
finalize_kernel(float* __restrict__ out) {
    const int n = blockIdx.x * THREADS + threadIdx.x;

    const unsigned long long pk = g_bestpk[n];
    const int bi = 8191 - (int)(pk & 0xFFFFFFFFull);
    const float best = finv((unsigned int)(pk >> 32));

    out[N_PTS * DIM + 2 + n] = (float)bi;
    atomicAdd(&g_hist[bi], 1);

    const float4* ep = reinterpret_cast<const float4*>(g_ew + bi * DIM);
    const int b  = n >> 10;
    const int hw = n & 1023;
    float* op = out + b * (DIM * 1024) + hw;
#pragma unroll
    for (int i = 0; i < 8; i++) {
        float4 e = ep[i];
        op[(4 * i + 0) * 1024] = e.x;
        op[(4 * i + 1) * 1024] = e.y;
        op[(4 * i + 2) * 1024] = e.z;
        op[(4 * i + 3) * 1024] = e.w;
    }

    __shared__ float red[THREADS];
    red[threadIdx.x] = 2.0f - 2.0f * best;
    __syncthreads();
#pragma unroll
    for (int st = THREADS / 2; st > 0; st >>= 1) {
        if (threadIdx.x < st) red[threadIdx.x] += red[threadIdx.x + st];
        __syncthreads();
    }
    if (threadIdx.x == 0) g_part[blockIdx.x] = red[0];
}

// ============================================================
// Kernel 7: entropy partials
// ============================================================
__global__ void ent_kernel() {
    const int bin = blockIdx.x * 256 + threadIdx.x;
    const float denom = (float)N_PTS + (float)K_EMB * 1e-4f;
    const float invd  = 1.0f / denom;
    float p = ((float)g_hist[bin] + 1e-4f) * invd;
    __shared__ float sh[256];
    sh[threadIdx.x] = p * logf(p);
    __syncthreads();
#pragma unroll
    for (int st = 128; st > 0; st >>= 1) {
        if (threadIdx.x < st) sh[threadIdx.x] += sh[threadIdx.x + st];
        __syncthreads();
    }
    if (threadIdx.x == 0) g_entp[blockIdx.x] = sh[0];
}

// ============================================================
// Kernel 8: final scalars
// ============================================================
__global__ void scalars_kernel(float* __restrict__ out) {
    const int t = threadIdx.x;
    __shared__ float sh[THREADS];

    sh[t] = (t < 32) ? g_entp[t] : 0.f;
    __syncthreads();
#pragma unroll
    for (int st = THREADS / 2; st > 0; st >>= 1) {
        if (t < st) sh[t] += sh[t + st];
        __syncthreads();
    }
    float entropy = -sh[0];
    __syncthreads();

    sh[t] = (t < NBLK) ? g_part[t] : 0.f;
    __syncthreads();
#pragma unroll
    for (int st = THREADS / 2; st > 0; st >>= 1) {
        if (t < st) sh[t] += sh[t + st];
        __syncthreads();
    }
    if (t == 0) {
        out[N_PTS * DIM + 0] = 1.25f * (sh[0] / (float)N_PTS);
        out[N_PTS * DIM + 1] = entropy;
    }
}

// ============================================================
extern "C" void kernel_launch(void* const* d_in, const int* in_sizes, int n_in,
                              void* d_out, int out_size) {
    const float* z   = (const float*)d_in[0];
    const float* emb = (const float*)d_in[1];
    if (n_in >= 2 && in_sizes[0] == K_EMB * DIM && in_sizes[1] == N_PTS * DIM) {
        z   = (const float*)d_in[1];
        emb = (const float*)d_in[0];
    }
    float* out = (float*)d_out;

    // raise dynamic smem limit (host-side, idempotent, capture-safe)
    cudaFuncSetAttribute(pass1_kernel,
                         cudaFuncAttributeMaxDynamicSharedMemorySize, SMEM_BYTES);
    cudaFuncSetAttribute(pass2_kernel,
                         cudaFuncAttributeMaxDynamicSharedMemorySize, SMEM_BYTES);

    prep_z_kernel<<<NBLK, THREADS>>>(z);                          // 1
    prep_emb_kernel<<<K_EMB / THREADS, THREADS>>>(emb);           // 2
    pass1_kernel<<<ITEMS, THREADS, SMEM_BYTES>>>();               // 3
    pass2_kernel<<<ITEMS, THREADS, SMEM_BYTES>>>();               // 4 (profiled)
    rescore_kernel<<<256, THREADS>>>();                           // 5
    finalize_kernel<<<NBLK, THREADS>>>(out);                      // 6
    ent_kernel<<<32, 256>>>();                                    // 7
    scalars_kernel<<<1, THREADS>>>(out);                          // 8
}